// round 9
// baseline (speedup 1.0000x reference)
#include <cuda_runtime.h>
#include <cuda_bf16.h>
#include <cstdint>
#include <math.h>

#define L 512
#define Dm 1024
#define NH 16
#define NKV 4
#define NR 16
#define HD 64
#define ATTN_SCALE 0.125f
#define REL_SCALE 0.125f

// ---------------- scratch ----------------------------------------------------
__device__ float g_Q[L * NH * HD];
__device__ float g_K[L * NKV * HD];
__device__ float g_QR[L * NR * HD];
__device__ float g_KR[L * NR * HD];
__device__ float g_SV[L * NKV * HD];
__device__ float g_S[L * NH * NR];
__device__ float g_CTX[L * NH * HD];
__device__ float g_RELT[NR * L * L];   // relations in [r][i][j]

__device__ __forceinline__ float to_tf32(float x) {
    uint32_t u;
    asm("cvt.rna.tf32.f32 %0, %1;" : "=r"(u) : "f"(x));
    return __uint_as_float(u);
}
__device__ __forceinline__ void mma_tf32(float c[4], uint32_t a0, uint32_t a1,
                                         uint32_t a2, uint32_t a3,
                                         uint32_t b0, uint32_t b1) {
    asm volatile(
        "mma.sync.aligned.m16n8k8.row.col.f32.tf32.tf32.f32 "
        "{%0,%1,%2,%3}, {%4,%5,%6,%7}, {%8,%9}, {%0,%1,%2,%3};"
        : "+f"(c[0]), "+f"(c[1]), "+f"(c[2]), "+f"(c[3])
        : "r"(a0), "r"(a1), "r"(a2), "r"(a3), "r"(b0), "r"(b1));
}
__device__ __forceinline__ float2 hl_split(float x) {
    float h = to_tf32(x);
    return make_float2(h, to_tf32(x - h));
}

// ---------------- pipelined tf32 GEMM, 128x128 tile (projections / out) ------
// 8 warps = 2(m) x 4(n); warp tile 64x32 = 4x4 m16n8k8 atoms.
__device__ __forceinline__ void mma_gemm_tile(
    const float* __restrict__ A, int lda,
    const float* __restrict__ W, int ldb,
    float* __restrict__ C, int ldc,
    int m0, int n0, int K,
    const float* __restrict__ fcos, const float* __restrict__ fsin, int ropef)
{
    __shared__ float As[128][36];    // [m][k]
    __shared__ float Bs[32][136];    // [k][n], 136 -> b-frag banks (8*tr+tq), conflict-free

    int tid = threadIdx.x;
    int warp = tid >> 5, lane = tid & 31;
    int tq = lane >> 2, tr = lane & 3;
    int wm = warp & 1, wn = warp >> 1;
    int mb = wm * 64, nb = wn * 32;

    float c[4][4][4];
    #pragma unroll
    for (int i = 0; i < 4; i++)
        #pragma unroll
        for (int j = 0; j < 4; j++)
            #pragma unroll
            for (int k = 0; k < 4; k++) c[i][j][k] = 0.f;

    float4 pa[4], pb[4];
    #pragma unroll
    for (int i = 0; i < 4; i++) {       // A: 128 rows x 32 k
        int e = tid + i * 256;
        int r = e >> 3, c4 = e & 7;
        pa[i] = *reinterpret_cast<const float4*>(&A[(size_t)(m0 + r) * lda + c4 * 4]);
    }
    #pragma unroll
    for (int i = 0; i < 4; i++) {       // B: 32 k x 128 n
        int e = tid + i * 256;
        int k = e >> 5, n4 = e & 31;
        pb[i] = *reinterpret_cast<const float4*>(&W[(size_t)k * ldb + n0 + n4 * 4]);
    }

    int nch = K >> 5;
    for (int kc = 0; kc < nch; kc++) {
        #pragma unroll
        for (int i = 0; i < 4; i++) {
            int e = tid + i * 256;
            int r = e >> 3, c4 = e & 7;
            float4 v = pa[i];
            v.x = to_tf32(v.x); v.y = to_tf32(v.y); v.z = to_tf32(v.z); v.w = to_tf32(v.w);
            *reinterpret_cast<float4*>(&As[r][c4 * 4]) = v;
        }
        #pragma unroll
        for (int i = 0; i < 4; i++) {
            int e = tid + i * 256;
            int k = e >> 5, n4 = e & 31;
            float4 v = pb[i];
            v.x = to_tf32(v.x); v.y = to_tf32(v.y); v.z = to_tf32(v.z); v.w = to_tf32(v.w);
            *reinterpret_cast<float4*>(&Bs[k][n4 * 4]) = v;
        }
        __syncthreads();
        if (kc + 1 < nch) {
            int k0n = (kc + 1) << 5;
            #pragma unroll
            for (int i = 0; i < 4; i++) {
                int e = tid + i * 256;
                int r = e >> 3, c4 = e & 7;
                pa[i] = *reinterpret_cast<const float4*>(&A[(size_t)(m0 + r) * lda + k0n + c4 * 4]);
            }
            #pragma unroll
            for (int i = 0; i < 4; i++) {
                int e = tid + i * 256;
                int k = e >> 5, n4 = e & 31;
                pb[i] = *reinterpret_cast<const float4*>(&W[(size_t)(k0n + k) * ldb + n0 + n4 * 4]);
            }
        }
        #pragma unroll
        for (int ks = 0; ks < 4; ks++) {
            int kb = ks * 8;
            uint32_t a[4][4], b[4][2];
            #pragma unroll
            for (int ma = 0; ma < 4; ma++) {
                int r0 = mb + ma * 16 + tq;
                a[ma][0] = __float_as_uint(As[r0][kb + tr]);
                a[ma][1] = __float_as_uint(As[r0 + 8][kb + tr]);
                a[ma][2] = __float_as_uint(As[r0][kb + tr + 4]);
                a[ma][3] = __float_as_uint(As[r0 + 8][kb + tr + 4]);
            }
            #pragma unroll
            for (int na = 0; na < 4; na++) {
                int n_ = nb + na * 8 + tq;
                b[na][0] = __float_as_uint(Bs[kb + tr][n_]);
                b[na][1] = __float_as_uint(Bs[kb + tr + 4][n_]);
            }
            #pragma unroll
            for (int ma = 0; ma < 4; ma++)
                #pragma unroll
                for (int na = 0; na < 4; na++)
                    mma_tf32(c[ma][na], a[ma][0], a[ma][1], a[ma][2], a[ma][3],
                             b[na][0], b[na][1]);
        }
        __syncthreads();
    }

    #pragma unroll
    for (int ma = 0; ma < 4; ma++) {
        int row = m0 + mb + ma * 16 + tq;
        #pragma unroll
        for (int na = 0; na < 4; na++) {
            int col = n0 + nb + na * 8 + 2 * tr;
            float v0 = c[ma][na][0], v1 = c[ma][na][1];
            float v2 = c[ma][na][2], v3 = c[ma][na][3];
            if (ropef) {
                int p = (col & 63) >> 1;
                float c0 = fcos[row * 32 + p], s0 = fsin[row * 32 + p];
                float c1 = fcos[(row + 8) * 32 + p], s1 = fsin[(row + 8) * 32 + p];
                float t0 = v0 * c0 - v1 * s0, t1 = v0 * s0 + v1 * c0;
                float t2 = v2 * c1 - v3 * s1, t3 = v2 * s1 + v3 * c1;
                v0 = t0; v1 = t1; v2 = t2; v3 = t3;
            }
            *reinterpret_cast<float2*>(&C[(size_t)row * ldc + col]) = make_float2(v0, v1);
            *reinterpret_cast<float2*>(&C[(size_t)(row + 8) * ldc + col]) = make_float2(v2, v3);
        }
    }
}

__global__ void __launch_bounds__(256) proj_mma_kernel(
    const float* __restrict__ x, const float* __restrict__ symbols,
    const float* __restrict__ wq, const float* __restrict__ wqr,
    const float* __restrict__ wkr, const float* __restrict__ wk,
    const float* __restrict__ wv,
    const float* __restrict__ fcos, const float* __restrict__ fsin,
    float* __restrict__ Q, float* __restrict__ Kp, float* __restrict__ QR,
    float* __restrict__ KR, float* __restrict__ SV)
{
    int mt = blockIdx.x;
    int t = blockIdx.y;
    const float* A = x;
    const float* W;
    float* C;
    int ldb, n0, ropef = 0;
    if (t < 8)       { W = wq;  C = Q;  ldb = 1024; n0 = t * 128; ropef = 1; }
    else if (t < 16) { W = wqr; C = QR; ldb = 1024; n0 = (t - 8) * 128; }
    else if (t < 24) { W = wkr; C = KR; ldb = 1024; n0 = (t - 16) * 128; }
    else if (t < 26) { W = wk;  C = Kp; ldb = 256;  n0 = (t - 24) * 128; ropef = 1; }
    else             { W = wv; A = symbols; C = SV; ldb = 256; n0 = (t - 26) * 128; }
    mma_gemm_tile(A, 1024, W, ldb, C, ldb, mt * 128, n0, 1024, fcos, fsin, ropef);
}

__global__ void __launch_bounds__(256) out_mma_kernel(
    const float* __restrict__ CTX, const float* __restrict__ wo, float* __restrict__ out)
{
    mma_gemm_tile(CTX, 1024, wo, 1024, out, 1024, blockIdx.x * 128, blockIdx.y * 128, 1024,
                  nullptr, nullptr, 0);
}

// ---------------- 3xTF32 core: (hi,lo) packed float2 smem, pipelined ---------
// BNK=1: B stored [n][k] rows at n0.  BNK=0: B stored [k][n], cols at n0.
template<int BNK>
__device__ __forceinline__ void mma3x_compute(
    const float* __restrict__ A, int lda,
    const float* __restrict__ B, int ldb,
    int m0, int n0, int kmax, float c[2][4][4])
{
    __shared__ float2 As[128][20];
    __shared__ float2 Bs[BNK ? 64 : 16][BNK ? 20 : 68];

    int tid = threadIdx.x;
    int warp = tid >> 5, lane = tid & 31;
    int tq = lane >> 2, tr = lane & 3;
    int wm = warp & 3, wn = warp >> 2;
    int mb = wm * 32, nb = wn * 32;

    float4 pa[2], pb;
    #pragma unroll
    for (int i = 0; i < 2; i++) {
        int e = tid + i * 256;
        int r = e >> 2, k4 = e & 3;
        pa[i] = *reinterpret_cast<const float4*>(&A[(size_t)(m0 + r) * lda + k4 * 4]);
    }
    if (BNK) {
        int r = tid >> 2, k4 = tid & 3;
        pb = *reinterpret_cast<const float4*>(&B[(size_t)(n0 + r) * ldb + k4 * 4]);
    } else {
        int k = tid >> 4, n4 = tid & 15;
        pb = *reinterpret_cast<const float4*>(&B[(size_t)k * ldb + n0 + n4 * 4]);
    }

    for (int k0 = 0; k0 < kmax; k0 += 16) {
        #pragma unroll
        for (int i = 0; i < 2; i++) {
            int e = tid + i * 256;
            int r = e >> 2, k4 = e & 3;
            float2 h0 = hl_split(pa[i].x), h1 = hl_split(pa[i].y);
            float2 h2 = hl_split(pa[i].z), h3 = hl_split(pa[i].w);
            *reinterpret_cast<float4*>(&As[r][k4 * 4]) =
                make_float4(h0.x, h0.y, h1.x, h1.y);
            *reinterpret_cast<float4*>(&As[r][k4 * 4 + 2]) =
                make_float4(h2.x, h2.y, h3.x, h3.y);
        }
        {
            float2 h0 = hl_split(pb.x), h1 = hl_split(pb.y);
            float2 h2 = hl_split(pb.z), h3 = hl_split(pb.w);
            if (BNK) {
                int r = tid >> 2, k4 = tid & 3;
                *reinterpret_cast<float4*>(&Bs[r][k4 * 4]) =
                    make_float4(h0.x, h0.y, h1.x, h1.y);
                *reinterpret_cast<float4*>(&Bs[r][k4 * 4 + 2]) =
                    make_float4(h2.x, h2.y, h3.x, h3.y);
            } else {
                int k = tid >> 4, n4 = tid & 15;
                *reinterpret_cast<float4*>(&Bs[k][n4 * 4]) =
                    make_float4(h0.x, h0.y, h1.x, h1.y);
                *reinterpret_cast<float4*>(&Bs[k][n4 * 4 + 2]) =
                    make_float4(h2.x, h2.y, h3.x, h3.y);
            }
        }
        __syncthreads();
        if (k0 + 16 < kmax) {
            int kn = k0 + 16;
            #pragma unroll
            for (int i = 0; i < 2; i++) {
                int e = tid + i * 256;
                int r = e >> 2, k4 = e & 3;
                pa[i] = *reinterpret_cast<const float4*>(&A[(size_t)(m0 + r) * lda + kn + k4 * 4]);
            }
            if (BNK) {
                int r = tid >> 2, k4 = tid & 3;
                pb = *reinterpret_cast<const float4*>(&B[(size_t)(n0 + r) * ldb + kn + k4 * 4]);
            } else {
                int k = tid >> 4, n4 = tid & 15;
                pb = *reinterpret_cast<const float4*>(&B[(size_t)(kn + k) * ldb + n0 + n4 * 4]);
            }
        }
        #pragma unroll
        for (int ks = 0; ks < 2; ks++) {
            int kb = ks * 8;
            float2 a0[2][4], b0[4][2];
            #pragma unroll
            for (int ma = 0; ma < 2; ma++) {
                int r0 = mb + ma * 16 + tq;
                a0[ma][0] = As[r0][kb + tr];
                a0[ma][1] = As[r0 + 8][kb + tr];
                a0[ma][2] = As[r0][kb + tr + 4];
                a0[ma][3] = As[r0 + 8][kb + tr + 4];
            }
            #pragma unroll
            for (int na = 0; na < 4; na++) {
                int n_ = nb + na * 8 + tq;
                if (BNK) {
                    b0[na][0] = Bs[n_][kb + tr];
                    b0[na][1] = Bs[n_][kb + tr + 4];
                } else {
                    b0[na][0] = Bs[kb + tr][n_];
                    b0[na][1] = Bs[kb + tr + 4][n_];
                }
            }
            #pragma unroll
            for (int ma = 0; ma < 2; ma++)
                #pragma unroll
                for (int na = 0; na < 4; na++) {
                    uint32_t ah0 = __float_as_uint(a0[ma][0].x), al0 = __float_as_uint(a0[ma][0].y);
                    uint32_t ah1 = __float_as_uint(a0[ma][1].x), al1 = __float_as_uint(a0[ma][1].y);
                    uint32_t ah2 = __float_as_uint(a0[ma][2].x), al2 = __float_as_uint(a0[ma][2].y);
                    uint32_t ah3 = __float_as_uint(a0[ma][3].x), al3 = __float_as_uint(a0[ma][3].y);
                    uint32_t bh0 = __float_as_uint(b0[na][0].x), bl0 = __float_as_uint(b0[na][0].y);
                    uint32_t bh1 = __float_as_uint(b0[na][1].x), bl1 = __float_as_uint(b0[na][1].y);
                    mma_tf32(c[ma][na], ah0, ah1, ah2, ah3, bl0, bl1);
                    mma_tf32(c[ma][na], al0, al1, al2, al3, bh0, bh1);
                    mma_tf32(c[ma][na], ah0, ah1, ah2, ah3, bh0, bh1);
                }
        }
        __syncthreads();
    }
}

// ---------------- fused scores + relations (3xTF32) --------------------------
__global__ void __launch_bounds__(256, 2) scorerel_kernel(
    const float* __restrict__ Q, const float* __restrict__ K,
    const float* __restrict__ QR, const float* __restrict__ KR,
    float* __restrict__ attn, float* __restrict__ relT)
{
    int z = blockIdx.z;
    int m0 = blockIdx.y * 128, n0 = blockIdx.x * 64;
    bool is_sc = (z < 16);
    if (is_sc && n0 >= m0 + 128) return;

    const float* A = is_sc ? (Q + z * HD) : (QR + (z - 16) * HD);
    const float* B = is_sc ? (K + (z >> 2) * HD) : (KR + (z - 16) * HD);
    int ldb = is_sc ? 256 : 1024;
    float* C = is_sc ? (attn + (size_t)z * L * L) : (relT + (size_t)(z - 16) * L * L);

    float c[2][4][4];
    #pragma unroll
    for (int i = 0; i < 2; i++)
        #pragma unroll
        for (int j = 0; j < 4; j++)
            #pragma unroll
            for (int k = 0; k < 4; k++) c[i][j][k] = 0.f;

    mma3x_compute<1>(A, 1024, B, ldb, m0, n0, 64, c);

    int lane = threadIdx.x & 31, warp = threadIdx.x >> 5;
    int tq = lane >> 2, tr = lane & 3;
    int mb = (warp & 3) * 32, nb = (warp >> 2) * 32;
    #pragma unroll
    for (int ma = 0; ma < 2; ma++) {
        int row = m0 + mb + ma * 16 + tq;
        #pragma unroll
        for (int na = 0; na < 4; na++) {
            int col = n0 + nb + na * 8 + 2 * tr;
            *reinterpret_cast<float2*>(&C[(size_t)row * L + col]) =
                make_float2(c[ma][na][0] * 0.125f, c[ma][na][1] * 0.125f);
            *reinterpret_cast<float2*>(&C[(size_t)(row + 8) * L + col]) =
                make_float2(c[ma][na][2] * 0.125f, c[ma][na][3] * 0.125f);
        }
    }
}

// ---------------- attended (3xTF32 attn@sv + S@wr) ---------------------------
__global__ void __launch_bounds__(256, 2) attended3x_kernel(
    const float* __restrict__ attn, const float* __restrict__ SV,
    const float* __restrict__ S, const float* __restrict__ wr,
    float* __restrict__ ctx)
{
    int h = blockIdx.y;
    int m0 = blockIdx.x * 128;
    int jmax = m0 + 128;

    float c[2][4][4];
    #pragma unroll
    for (int i = 0; i < 2; i++)
        #pragma unroll
        for (int j = 0; j < 4; j++)
            #pragma unroll
            for (int k = 0; k < 4; k++) c[i][j][k] = 0.f;

    mma3x_compute<0>(attn + (size_t)h * L * L, L, SV + (h >> 2) * HD, 256, m0, 0, jmax, c);

    __shared__ float wrs[16][64];
    __shared__ float Ss[128][17];
    int tid = threadIdx.x;
    for (int t = tid; t < 16 * 64; t += 256) {
        int rr = t >> 6, n = t & 63;
        wrs[rr][n] = wr[(size_t)rr * (NH * HD) + h * HD + n];
    }
    for (int t = tid; t < 128 * 16; t += 256) {
        int m = t >> 4, rr = t & 15;
        Ss[m][rr] = S[((size_t)(m0 + m) * NH + h) * NR + rr];
    }
    __syncthreads();

    int lane = tid & 31, warp = tid >> 5;
    int tq = lane >> 2, tr = lane & 3;
    int mb = (warp & 3) * 32, nb = (warp >> 2) * 32;
    #pragma unroll
    for (int rr = 0; rr < 16; rr++) {
        #pragma unroll
        for (int ma = 0; ma < 2; ma++) {
            float s0 = Ss[mb + ma * 16 + tq][rr];
            float s1 = Ss[mb + ma * 16 + tq + 8][rr];
            #pragma unroll
            for (int na = 0; na < 4; na++) {
                int col = nb + na * 8 + 2 * tr;
                float w0 = wrs[rr][col], w1 = wrs[rr][col + 1];
                c[ma][na][0] += s0 * w0; c[ma][na][1] += s0 * w1;
                c[ma][na][2] += s1 * w0; c[ma][na][3] += s1 * w1;
            }
        }
    }
    #pragma unroll
    for (int ma = 0; ma < 2; ma++) {
        int row = m0 + mb + ma * 16 + tq;
        #pragma unroll
        for (int na = 0; na < 4; na++) {
            int col = h * HD + nb + na * 8 + 2 * tr;
            *reinterpret_cast<float2*>(&ctx[(size_t)row * (NH * HD) + col]) =
                make_float2(c[ma][na][0], c[ma][na][1]);
            *reinterpret_cast<float2*>(&ctx[(size_t)(row + 8) * (NH * HD) + col]) =
                make_float2(c[ma][na][2], c[ma][na][3]);
        }
    }
}

// ---------------- causal softmax ---------------------------------------------
__global__ void __launch_bounds__(128) softmax_kernel(float* __restrict__ attn) {
    int row = blockIdx.x;
    int i = row & (L - 1);
    int len = i + 1;
    float4* p4 = reinterpret_cast<float4*>(attn + (size_t)row * L);
    int tid = threadIdx.x;
    int lane = tid & 31, wid = tid >> 5;
    int base = tid * 4;

    float4 v = p4[tid];
    float e0 = (base + 0 < len) ? v.x : -3.0e38f;
    float e1 = (base + 1 < len) ? v.y : -3.0e38f;
    float e2 = (base + 2 < len) ? v.z : -3.0e38f;
    float e3 = (base + 3 < len) ? v.w : -3.0e38f;

    float m = fmaxf(fmaxf(e0, e1), fmaxf(e2, e3));
    #pragma unroll
    for (int off = 16; off > 0; off >>= 1)
        m = fmaxf(m, __shfl_xor_sync(0xFFFFFFFFu, m, off));

    __shared__ float sm[8];
    if (lane == 0) sm[wid] = m;
    __syncthreads();
    m = fmaxf(fmaxf(sm[0], sm[1]), fmaxf(sm[2], sm[3]));

    float x0 = (base + 0 < len) ? __expf(e0 - m) : 0.f;
    float x1 = (base + 1 < len) ? __expf(e1 - m) : 0.f;
    float x2 = (base + 2 < len) ? __expf(e2 - m) : 0.f;
    float x3 = (base + 3 < len) ? __expf(e3 - m) : 0.f;

    float s = x0 + x1 + x2 + x3;
    #pragma unroll
    for (int off = 16; off > 0; off >>= 1)
        s += __shfl_xor_sync(0xFFFFFFFFu, s, off);
    if (lane == 0) sm[4 + wid] = s;
    __syncthreads();
    float inv = 1.f / (sm[4] + sm[5] + sm[6] + sm[7]);

    p4[tid] = make_float4(x0 * inv, x1 * inv, x2 * inv, x3 * inv);
}

// ---- fused: rel[i][j][r] transpose-write + S[i,h,r] accumulation ------------
__global__ void __launch_bounds__(256) s_trans_kernel(
    const float* __restrict__ attn, const float* __restrict__ relT,
    float* __restrict__ rel, float* __restrict__ S)
{
    int i = blockIdx.x;
    int tid = threadIdx.x;
    int h = tid >> 4, r = tid & 15;
    __shared__ float attnS[16][136];
    __shared__ float relS[16][136];
    float acc = 0.f;
    for (int j0 = 0; j0 < L; j0 += 128) {
        #pragma unroll
        for (int e = tid; e < 512; e += 256) {
            int hh = e >> 5, q = e & 31;
            *reinterpret_cast<float4*>(&attnS[hh][q * 4]) =
                *reinterpret_cast<const float4*>(&attn[((size_t)hh * L + i) * L + j0 + q * 4]);
        }
        #pragma unroll
        for (int e = tid; e < 512; e += 256) {
            int rr = e >> 5, q = e & 31;
            *reinterpret_cast<float4*>(&relS[rr][q * 4]) =
                *reinterpret_cast<const float4*>(&relT[((size_t)rr * L + i) * L + j0 + q * 4]);
        }
        __syncthreads();
        // transposed write of the rel output
        #pragma unroll
        for (int e = tid; e < 512; e += 256) {
            int j = e >> 2, rq = e & 3;
            float4 v = make_float4(relS[rq * 4 + 0][j], relS[rq * 4 + 1][j],
                                   relS[rq * 4 + 2][j], relS[rq * 4 + 3][j]);
            *reinterpret_cast<float4*>(&rel[((size_t)i * L + j0 + j) * NR + rq * 4]) = v;
        }
        // S accumulation, vectorized: 4 MACs per 2 LDS.128
        const float4* a4 = reinterpret_cast<const float4*>(&attnS[h][0]);
        const float4* r4 = reinterpret_cast<const float4*>(&relS[r][0]);
        #pragma unroll 8
        for (int q = 0; q < 32; q++) {
            float4 av = a4[q], rv = r4[q];
            acc += av.x * rv.x + av.y * rv.y + av.z * rv.z + av.w * rv.w;
        }
        __syncthreads();
    }
    S[((size_t)i * NH + h) * NR + r] = acc;
}

// ---------------------------------------------------------------------------
extern "C" void kernel_launch(void* const* d_in, const int* in_sizes, int n_in,
                              void* d_out, int out_size) {
    const float* x       = (const float*)d_in[0];
    const float* symbols = (const float*)d_in[1];
    const float* fcos    = (const float*)d_in[2];
    const float* fsin    = (const float*)d_in[3];
    const float* wq_attn = (const float*)d_in[4];
    const float* wk_attn = (const float*)d_in[5];
    const float* wq_rel  = (const float*)d_in[6];
    const float* wk_rel  = (const float*)d_in[7];
    const float* wr      = (const float*)d_in[8];
    const float* wv      = (const float*)d_in[9];
    const float* wo      = (const float*)d_in[10];

    float* out  = (float*)d_out;
    float* attn = out + (size_t)L * NH * HD;
    float* rel  = attn + (size_t)NH * L * L;

    float *Q, *K, *QR, *KR, *SV, *S, *CTX, *RELT;
    cudaGetSymbolAddress((void**)&Q,  g_Q);
    cudaGetSymbolAddress((void**)&K,  g_K);
    cudaGetSymbolAddress((void**)&QR, g_QR);
    cudaGetSymbolAddress((void**)&KR, g_KR);
    cudaGetSymbolAddress((void**)&SV, g_SV);
    cudaGetSymbolAddress((void**)&S,  g_S);
    cudaGetSymbolAddress((void**)&CTX, g_CTX);
    cudaGetSymbolAddress((void**)&RELT, g_RELT);

    // 1) projections + fused RoPE (128x128 tiles)
    proj_mma_kernel<<<dim3(4, 28), 256>>>(x, symbols, wq_attn, wq_rel, wk_rel,
                                          wk_attn, wv, fcos, fsin, Q, K, QR, KR, SV);

    // 2) fused scores + relations (3xTF32)
    scorerel_kernel<<<dim3(8, 4, 32), 256>>>(Q, K, QR, KR, attn, RELT);

    // 3) softmax
    softmax_kernel<<<NH * L, 128>>>(attn);

    // 4) fused rel transpose-out + S factorization (float4 accumulation)
    s_trans_kernel<<<L, 256>>>(attn, RELT, rel, S);

    // 5) ctx = attn@sv (3xTF32) + S@wr
    attended3x_kernel<<<dim3(4, NH), 256>>>(attn, SV, S, wr, CTX);

    // 6) out = ctx @ wo (128x128 tiles)
    out_mma_kernel<<<dim3(4, 8), 256>>>(CTX, wo, out);
}

// round 10
// speedup vs baseline: 1.6241x; 1.6241x over previous
#include <cuda_runtime.h>
#include <cuda_bf16.h>
#include <cstdint>
#include <math.h>

#define L 512
#define Dm 1024
#define NH 16
#define NKV 4
#define NR 16
#define HD 64
#define ATTN_SCALE 0.125f
#define REL_SCALE 0.125f

// ---------------- scratch ----------------------------------------------------
__device__ float g_Q[L * NH * HD];
__device__ float g_K[L * NKV * HD];
__device__ float g_QR[L * NR * HD];
__device__ float g_KR[L * NR * HD];
__device__ float g_SV[L * NKV * HD];
__device__ float g_S[L * NH * NR];
__device__ float g_CTX[L * NH * HD];
__device__ float g_RELT[NR * L * L];   // relations in [r][i][j]

__device__ __forceinline__ float to_tf32(float x) {
    uint32_t u;
    asm("cvt.rna.tf32.f32 %0, %1;" : "=r"(u) : "f"(x));
    return __uint_as_float(u);
}
__device__ __forceinline__ void mma_tf32(float c[4], uint32_t a0, uint32_t a1,
                                         uint32_t a2, uint32_t a3,
                                         uint32_t b0, uint32_t b1) {
    asm volatile(
        "mma.sync.aligned.m16n8k8.row.col.f32.tf32.tf32.f32 "
        "{%0,%1,%2,%3}, {%4,%5,%6,%7}, {%8,%9}, {%0,%1,%2,%3};"
        : "+f"(c[0]), "+f"(c[1]), "+f"(c[2]), "+f"(c[3])
        : "r"(a0), "r"(a1), "r"(a2), "r"(a3), "r"(b0), "r"(b1));
}
__device__ __forceinline__ float2 hl_split(float x) {
    float h = to_tf32(x);
    return make_float2(h, to_tf32(x - h));
}

// ---------------- pipelined tf32 GEMM tile 128x64 (projections / out) --------
__device__ __forceinline__ void mma_gemm_tile(
    const float* __restrict__ A, int lda,
    const float* __restrict__ W, int ldb,
    float* __restrict__ C, int ldc,
    int m0, int n0, int K,
    const float* __restrict__ fcos, const float* __restrict__ fsin, int ropef)
{
    __shared__ float As[128][36];
    __shared__ float Bs[32][72];

    int tid = threadIdx.x;
    int warp = tid >> 5, lane = tid & 31;
    int tq = lane >> 2, tr = lane & 3;
    int wm = warp & 3, wn = warp >> 2;
    int mb = wm * 32, nb = wn * 32;

    float c[2][4][4];
    #pragma unroll
    for (int i = 0; i < 2; i++)
        #pragma unroll
        for (int j = 0; j < 4; j++)
            #pragma unroll
            for (int k = 0; k < 4; k++) c[i][j][k] = 0.f;

    float4 pa[4], pb[2];
    #pragma unroll
    for (int i = 0; i < 4; i++) {
        int e = tid + i * 256;
        int r = e >> 3, c4 = e & 7;
        pa[i] = *reinterpret_cast<const float4*>(&A[(size_t)(m0 + r) * lda + c4 * 4]);
    }
    #pragma unroll
    for (int i = 0; i < 2; i++) {
        int e = tid + i * 256;
        int k = e >> 4, n4 = e & 15;
        pb[i] = *reinterpret_cast<const float4*>(&W[(size_t)k * ldb + n0 + n4 * 4]);
    }

    int nch = K >> 5;
    for (int kc = 0; kc < nch; kc++) {
        #pragma unroll
        for (int i = 0; i < 4; i++) {
            int e = tid + i * 256;
            int r = e >> 3, c4 = e & 7;
            float4 v = pa[i];
            v.x = to_tf32(v.x); v.y = to_tf32(v.y); v.z = to_tf32(v.z); v.w = to_tf32(v.w);
            *reinterpret_cast<float4*>(&As[r][c4 * 4]) = v;
        }
        #pragma unroll
        for (int i = 0; i < 2; i++) {
            int e = tid + i * 256;
            int k = e >> 4, n4 = e & 15;
            float4 v = pb[i];
            v.x = to_tf32(v.x); v.y = to_tf32(v.y); v.z = to_tf32(v.z); v.w = to_tf32(v.w);
            *reinterpret_cast<float4*>(&Bs[k][n4 * 4]) = v;
        }
        __syncthreads();
        if (kc + 1 < nch) {
            int k0n = (kc + 1) << 5;
            #pragma unroll
            for (int i = 0; i < 4; i++) {
                int e = tid + i * 256;
                int r = e >> 3, c4 = e & 7;
                pa[i] = *reinterpret_cast<const float4*>(&A[(size_t)(m0 + r) * lda + k0n + c4 * 4]);
            }
            #pragma unroll
            for (int i = 0; i < 2; i++) {
                int e = tid + i * 256;
                int k = e >> 4, n4 = e & 15;
                pb[i] = *reinterpret_cast<const float4*>(&W[(size_t)(k0n + k) * ldb + n0 + n4 * 4]);
            }
        }
        #pragma unroll
        for (int ks = 0; ks < 4; ks++) {
            int kb = ks * 8;
            uint32_t a[2][4], b[4][2];
            #pragma unroll
            for (int ma = 0; ma < 2; ma++) {
                int r0 = mb + ma * 16 + tq;
                a[ma][0] = __float_as_uint(As[r0][kb + tr]);
                a[ma][1] = __float_as_uint(As[r0 + 8][kb + tr]);
                a[ma][2] = __float_as_uint(As[r0][kb + tr + 4]);
                a[ma][3] = __float_as_uint(As[r0 + 8][kb + tr + 4]);
            }
            #pragma unroll
            for (int na = 0; na < 4; na++) {
                int n_ = nb + na * 8 + tq;
                b[na][0] = __float_as_uint(Bs[kb + tr][n_]);
                b[na][1] = __float_as_uint(Bs[kb + tr + 4][n_]);
            }
            #pragma unroll
            for (int ma = 0; ma < 2; ma++)
                #pragma unroll
                for (int na = 0; na < 4; na++)
                    mma_tf32(c[ma][na], a[ma][0], a[ma][1], a[ma][2], a[ma][3],
                             b[na][0], b[na][1]);
        }
        __syncthreads();
    }

    #pragma unroll
    for (int ma = 0; ma < 2; ma++) {
        int row = m0 + mb + ma * 16 + tq;
        #pragma unroll
        for (int na = 0; na < 4; na++) {
            int col = n0 + nb + na * 8 + 2 * tr;
            float v0 = c[ma][na][0], v1 = c[ma][na][1];
            float v2 = c[ma][na][2], v3 = c[ma][na][3];
            if (ropef) {
                int p = (col & 63) >> 1;
                float c0 = fcos[row * 32 + p], s0 = fsin[row * 32 + p];
                float c1 = fcos[(row + 8) * 32 + p], s1 = fsin[(row + 8) * 32 + p];
                float t0 = v0 * c0 - v1 * s0, t1 = v0 * s0 + v1 * c0;
                float t2 = v2 * c1 - v3 * s1, t3 = v2 * s1 + v3 * c1;
                v0 = t0; v1 = t1; v2 = t2; v3 = t3;
            }
            *reinterpret_cast<float2*>(&C[(size_t)row * ldc + col]) = make_float2(v0, v1);
            *reinterpret_cast<float2*>(&C[(size_t)(row + 8) * ldc + col]) = make_float2(v2, v3);
        }
    }
}

__global__ void __launch_bounds__(256, 2) proj_mma_kernel(
    const float* __restrict__ x, const float* __restrict__ symbols,
    const float* __restrict__ wq, const float* __restrict__ wqr,
    const float* __restrict__ wkr, const float* __restrict__ wk,
    const float* __restrict__ wv,
    const float* __restrict__ fcos, const float* __restrict__ fsin,
    float* __restrict__ Q, float* __restrict__ Kp, float* __restrict__ QR,
    float* __restrict__ KR, float* __restrict__ SV)
{
    int mt = blockIdx.x;
    int t = blockIdx.y;
    const float* A = x;
    const float* W;
    float* C;
    int ldb, n0, ropef = 0;
    if (t < 16)      { W = wq;  C = Q;  ldb = 1024; n0 = t * 64; ropef = 1; }
    else if (t < 32) { W = wqr; C = QR; ldb = 1024; n0 = (t - 16) * 64; }
    else if (t < 48) { W = wkr; C = KR; ldb = 1024; n0 = (t - 32) * 64; }
    else if (t < 52) { W = wk;  C = Kp; ldb = 256;  n0 = (t - 48) * 64; ropef = 1; }
    else             { W = wv; A = symbols; C = SV; ldb = 256; n0 = (t - 52) * 64; }
    mma_gemm_tile(A, 1024, W, ldb, C, ldb, mt * 128, n0, 1024, fcos, fsin, ropef);
}

__global__ void __launch_bounds__(256, 2) out_mma_kernel(
    const float* __restrict__ CTX, const float* __restrict__ wo, float* __restrict__ out)
{
    mma_gemm_tile(CTX, 1024, wo, 1024, out, 1024, blockIdx.x * 128, blockIdx.y * 64, 1024,
                  nullptr, nullptr, 0);
}

// ---------------- 3xTF32 core: (hi,lo) packed float2 smem, pipelined ---------
template<int BNK>
__device__ __forceinline__ void mma3x_compute(
    const float* __restrict__ A, int lda,
    const float* __restrict__ B, int ldb,
    int m0, int n0, int kmax, float c[2][4][4])
{
    __shared__ float2 As[128][20];
    __shared__ float2 Bs[BNK ? 64 : 16][BNK ? 20 : 68];

    int tid = threadIdx.x;
    int warp = tid >> 5, lane = tid & 31;
    int tq = lane >> 2, tr = lane & 3;
    int wm = warp & 3, wn = warp >> 2;
    int mb = wm * 32, nb = wn * 32;

    float4 pa[2], pb;
    #pragma unroll
    for (int i = 0; i < 2; i++) {
        int e = tid + i * 256;
        int r = e >> 2, k4 = e & 3;
        pa[i] = *reinterpret_cast<const float4*>(&A[(size_t)(m0 + r) * lda + k4 * 4]);
    }
    if (BNK) {
        int r = tid >> 2, k4 = tid & 3;
        pb = *reinterpret_cast<const float4*>(&B[(size_t)(n0 + r) * ldb + k4 * 4]);
    } else {
        int k = tid >> 4, n4 = tid & 15;
        pb = *reinterpret_cast<const float4*>(&B[(size_t)k * ldb + n0 + n4 * 4]);
    }

    for (int k0 = 0; k0 < kmax; k0 += 16) {
        #pragma unroll
        for (int i = 0; i < 2; i++) {
            int e = tid + i * 256;
            int r = e >> 2, k4 = e & 3;
            float2 h0 = hl_split(pa[i].x), h1 = hl_split(pa[i].y);
            float2 h2 = hl_split(pa[i].z), h3 = hl_split(pa[i].w);
            *reinterpret_cast<float4*>(&As[r][k4 * 4]) =
                make_float4(h0.x, h0.y, h1.x, h1.y);
            *reinterpret_cast<float4*>(&As[r][k4 * 4 + 2]) =
                make_float4(h2.x, h2.y, h3.x, h3.y);
        }
        {
            float2 h0 = hl_split(pb.x), h1 = hl_split(pb.y);
            float2 h2 = hl_split(pb.z), h3 = hl_split(pb.w);
            if (BNK) {
                int r = tid >> 2, k4 = tid & 3;
                *reinterpret_cast<float4*>(&Bs[r][k4 * 4]) =
                    make_float4(h0.x, h0.y, h1.x, h1.y);
                *reinterpret_cast<float4*>(&Bs[r][k4 * 4 + 2]) =
                    make_float4(h2.x, h2.y, h3.x, h3.y);
            } else {
                int k = tid >> 4, n4 = tid & 15;
                *reinterpret_cast<float4*>(&Bs[k][n4 * 4]) =
                    make_float4(h0.x, h0.y, h1.x, h1.y);
                *reinterpret_cast<float4*>(&Bs[k][n4 * 4 + 2]) =
                    make_float4(h2.x, h2.y, h3.x, h3.y);
            }
        }
        __syncthreads();
        if (k0 + 16 < kmax) {
            int kn = k0 + 16;
            #pragma unroll
            for (int i = 0; i < 2; i++) {
                int e = tid + i * 256;
                int r = e >> 2, k4 = e & 3;
                pa[i] = *reinterpret_cast<const float4*>(&A[(size_t)(m0 + r) * lda + kn + k4 * 4]);
            }
            if (BNK) {
                int r = tid >> 2, k4 = tid & 3;
                pb = *reinterpret_cast<const float4*>(&B[(size_t)(n0 + r) * ldb + kn + k4 * 4]);
            } else {
                int k = tid >> 4, n4 = tid & 15;
                pb = *reinterpret_cast<const float4*>(&B[(size_t)(kn + k) * ldb + n0 + n4 * 4]);
            }
        }
        #pragma unroll
        for (int ks = 0; ks < 2; ks++) {
            int kb = ks * 8;
            float2 a0[2][4], b0[4][2];
            #pragma unroll
            for (int ma = 0; ma < 2; ma++) {
                int r0 = mb + ma * 16 + tq;
                a0[ma][0] = As[r0][kb + tr];
                a0[ma][1] = As[r0 + 8][kb + tr];
                a0[ma][2] = As[r0][kb + tr + 4];
                a0[ma][3] = As[r0 + 8][kb + tr + 4];
            }
            #pragma unroll
            for (int na = 0; na < 4; na++) {
                int n_ = nb + na * 8 + tq;
                if (BNK) {
                    b0[na][0] = Bs[n_][kb + tr];
                    b0[na][1] = Bs[n_][kb + tr + 4];
                } else {
                    b0[na][0] = Bs[kb + tr][n_];
                    b0[na][1] = Bs[kb + tr + 4][n_];
                }
            }
            #pragma unroll
            for (int ma = 0; ma < 2; ma++)
                #pragma unroll
                for (int na = 0; na < 4; na++) {
                    uint32_t ah0 = __float_as_uint(a0[ma][0].x), al0 = __float_as_uint(a0[ma][0].y);
                    uint32_t ah1 = __float_as_uint(a0[ma][1].x), al1 = __float_as_uint(a0[ma][1].y);
                    uint32_t ah2 = __float_as_uint(a0[ma][2].x), al2 = __float_as_uint(a0[ma][2].y);
                    uint32_t ah3 = __float_as_uint(a0[ma][3].x), al3 = __float_as_uint(a0[ma][3].y);
                    uint32_t bh0 = __float_as_uint(b0[na][0].x), bl0 = __float_as_uint(b0[na][0].y);
                    uint32_t bh1 = __float_as_uint(b0[na][1].x), bl1 = __float_as_uint(b0[na][1].y);
                    mma_tf32(c[ma][na], ah0, ah1, ah2, ah3, bl0, bl1);
                    mma_tf32(c[ma][na], al0, al1, al2, al3, bh0, bh1);
                    mma_tf32(c[ma][na], ah0, ah1, ah2, ah3, bh0, bh1);
                }
        }
        __syncthreads();
    }
}

// ---------------- fused scores + relations (3xTF32) --------------------------
__global__ void __launch_bounds__(256, 2) scorerel_kernel(
    const float* __restrict__ Q, const float* __restrict__ K,
    const float* __restrict__ QR, const float* __restrict__ KR,
    float* __restrict__ attn, float* __restrict__ relT)
{
    int z = blockIdx.z;
    int m0 = blockIdx.y * 128, n0 = blockIdx.x * 64;
    bool is_sc = (z < 16);
    if (is_sc && n0 >= m0 + 128) return;

    const float* A = is_sc ? (Q + z * HD) : (QR + (z - 16) * HD);
    const float* B = is_sc ? (K + (z >> 2) * HD) : (KR + (z - 16) * HD);
    int ldb = is_sc ? 256 : 1024;
    float* C = is_sc ? (attn + (size_t)z * L * L) : (relT + (size_t)(z - 16) * L * L);

    float c[2][4][4];
    #pragma unroll
    for (int i = 0; i < 2; i++)
        #pragma unroll
        for (int j = 0; j < 4; j++)
            #pragma unroll
            for (int k = 0; k < 4; k++) c[i][j][k] = 0.f;

    mma3x_compute<1>(A, 1024, B, ldb, m0, n0, 64, c);

    int lane = threadIdx.x & 31, warp = threadIdx.x >> 5;
    int tq = lane >> 2, tr = lane & 3;
    int mb = (warp & 3) * 32, nb = (warp >> 2) * 32;
    #pragma unroll
    for (int ma = 0; ma < 2; ma++) {
        int row = m0 + mb + ma * 16 + tq;
        #pragma unroll
        for (int na = 0; na < 4; na++) {
            int col = n0 + nb + na * 8 + 2 * tr;
            *reinterpret_cast<float2*>(&C[(size_t)row * L + col]) =
                make_float2(c[ma][na][0] * 0.125f, c[ma][na][1] * 0.125f);
            *reinterpret_cast<float2*>(&C[(size_t)(row + 8) * L + col]) =
                make_float2(c[ma][na][2] * 0.125f, c[ma][na][3] * 0.125f);
        }
    }
}

// ---------------- attended (3xTF32 attn@sv + S@wr) ---------------------------
__global__ void __launch_bounds__(256, 2) attended3x_kernel(
    const float* __restrict__ attn, const float* __restrict__ SV,
    const float* __restrict__ S, const float* __restrict__ wr,
    float* __restrict__ ctx)
{
    int h = blockIdx.y;
    int m0 = blockIdx.x * 128;
    int jmax = m0 + 128;

    float c[2][4][4];
    #pragma unroll
    for (int i = 0; i < 2; i++)
        #pragma unroll
        for (int j = 0; j < 4; j++)
            #pragma unroll
            for (int k = 0; k < 4; k++) c[i][j][k] = 0.f;

    mma3x_compute<0>(attn + (size_t)h * L * L, L, SV + (h >> 2) * HD, 256, m0, 0, jmax, c);

    __shared__ float wrs[16][64];
    __shared__ float Ss[128][17];
    int tid = threadIdx.x;
    for (int t = tid; t < 16 * 64; t += 256) {
        int rr = t >> 6, n = t & 63;
        wrs[rr][n] = wr[(size_t)rr * (NH * HD) + h * HD + n];
    }
    for (int t = tid; t < 128 * 16; t += 256) {
        int m = t >> 4, rr = t & 15;
        Ss[m][rr] = S[((size_t)(m0 + m) * NH + h) * NR + rr];
    }
    __syncthreads();

    int lane = tid & 31, warp = tid >> 5;
    int tq = lane >> 2, tr = lane & 3;
    int mb = (warp & 3) * 32, nb = (warp >> 2) * 32;
    #pragma unroll
    for (int rr = 0; rr < 16; rr++) {
        #pragma unroll
        for (int ma = 0; ma < 2; ma++) {
            float s0 = Ss[mb + ma * 16 + tq][rr];
            float s1 = Ss[mb + ma * 16 + tq + 8][rr];
            #pragma unroll
            for (int na = 0; na < 4; na++) {
                int col = nb + na * 8 + 2 * tr;
                float w0 = wrs[rr][col], w1 = wrs[rr][col + 1];
                c[ma][na][0] += s0 * w0; c[ma][na][1] += s0 * w1;
                c[ma][na][2] += s1 * w0; c[ma][na][3] += s1 * w1;
            }
        }
    }
    #pragma unroll
    for (int ma = 0; ma < 2; ma++) {
        int row = m0 + mb + ma * 16 + tq;
        #pragma unroll
        for (int na = 0; na < 4; na++) {
            int col = h * HD + nb + na * 8 + 2 * tr;
            *reinterpret_cast<float2*>(&ctx[(size_t)row * (NH * HD) + col]) =
                make_float2(c[ma][na][0], c[ma][na][1]);
            *reinterpret_cast<float2*>(&ctx[(size_t)(row + 8) * (NH * HD) + col]) =
                make_float2(c[ma][na][2], c[ma][na][3]);
        }
    }
}

// ---------------- causal softmax ---------------------------------------------
__global__ void __launch_bounds__(128) softmax_kernel(float* __restrict__ attn) {
    int row = blockIdx.x;
    int i = row & (L - 1);
    int len = i + 1;
    float4* p4 = reinterpret_cast<float4*>(attn + (size_t)row * L);
    int tid = threadIdx.x;
    int lane = tid & 31, wid = tid >> 5;
    int base = tid * 4;

    float4 v = p4[tid];
    float e0 = (base + 0 < len) ? v.x : -3.0e38f;
    float e1 = (base + 1 < len) ? v.y : -3.0e38f;
    float e2 = (base + 2 < len) ? v.z : -3.0e38f;
    float e3 = (base + 3 < len) ? v.w : -3.0e38f;

    float m = fmaxf(fmaxf(e0, e1), fmaxf(e2, e3));
    #pragma unroll
    for (int off = 16; off > 0; off >>= 1)
        m = fmaxf(m, __shfl_xor_sync(0xFFFFFFFFu, m, off));

    __shared__ float sm[8];
    if (lane == 0) sm[wid] = m;
    __syncthreads();
    m = fmaxf(fmaxf(sm[0], sm[1]), fmaxf(sm[2], sm[3]));

    float x0 = (base + 0 < len) ? __expf(e0 - m) : 0.f;
    float x1 = (base + 1 < len) ? __expf(e1 - m) : 0.f;
    float x2 = (base + 2 < len) ? __expf(e2 - m) : 0.f;
    float x3 = (base + 3 < len) ? __expf(e3 - m) : 0.f;

    float s = x0 + x1 + x2 + x3;
    #pragma unroll
    for (int off = 16; off > 0; off >>= 1)
        s += __shfl_xor_sync(0xFFFFFFFFu, s, off);
    if (lane == 0) sm[4 + wid] = s;
    __syncthreads();
    float inv = 1.f / (sm[4] + sm[5] + sm[6] + sm[7]);

    p4[tid] = make_float4(x0 * inv, x1 * inv, x2 * inv, x3 * inv);
}

// ---- fused: rel[i][j][r] transpose-write + S[i,h,r] (r-quad, interleaved js) -
__global__ void __launch_bounds__(256) s_trans_kernel(
    const float* __restrict__ attn, const float* __restrict__ relT,
    float* __restrict__ rel, float* __restrict__ S)
{
    int i = blockIdx.x;
    int tid = threadIdx.x;
    int h  = tid >> 4;          // 0..15
    int rq = (tid >> 2) & 3;    // 0..3 (r-quad)
    int js = tid & 3;           // 0..3 (interleaved j-slice)
    __shared__ float attnS[16][132];
    __shared__ float relS[16][132];
    float4 acc = make_float4(0.f, 0.f, 0.f, 0.f);
    for (int j0 = 0; j0 < L; j0 += 128) {
        #pragma unroll
        for (int e = tid; e < 512; e += 256) {
            int hh = e >> 5, q = e & 31;
            *reinterpret_cast<float4*>(&attnS[hh][q * 4]) =
                *reinterpret_cast<const float4*>(&attn[((size_t)hh * L + i) * L + j0 + q * 4]);
        }
        #pragma unroll
        for (int e = tid; e < 512; e += 256) {
            int rr = e >> 5, q = e & 31;
            *reinterpret_cast<float4*>(&relS[rr][q * 4]) =
                *reinterpret_cast<const float4*>(&relT[((size_t)rr * L + i) * L + j0 + q * 4]);
        }
        __syncthreads();
        // transposed write of the rel output (as round 8)
        #pragma unroll
        for (int e = tid; e < 512; e += 256) {
            int j = e >> 2, q = e & 3;
            float4 v = make_float4(relS[q * 4 + 0][j], relS[q * 4 + 1][j],
                                   relS[q * 4 + 2][j], relS[q * 4 + 3][j]);
            *reinterpret_cast<float4*>(&rel[((size_t)i * L + j0 + j) * NR + q * 4]) = v;
        }
        // S accumulation: r-quad per thread, interleaved j (jc = 4*jj + js)
        // a-load banks (4h+4jj+js): conflict-free; rel 2-way (rq0/rq2).
        int r0 = rq * 4;
        #pragma unroll 8
        for (int jj = 0; jj < 32; jj++) {
            int jc = 4 * jj + js;
            float a = attnS[h][jc];
            acc.x += a * relS[r0 + 0][jc];
            acc.y += a * relS[r0 + 1][jc];
            acc.z += a * relS[r0 + 2][jc];
            acc.w += a * relS[r0 + 3][jc];
        }
        __syncthreads();
    }
    // reduce across the 4 js lanes (lanes differ in bits 0..1)
    #pragma unroll
    for (int off = 1; off < 4; off <<= 1) {
        acc.x += __shfl_xor_sync(0xFFFFFFFFu, acc.x, off);
        acc.y += __shfl_xor_sync(0xFFFFFFFFu, acc.y, off);
        acc.z += __shfl_xor_sync(0xFFFFFFFFu, acc.z, off);
        acc.w += __shfl_xor_sync(0xFFFFFFFFu, acc.w, off);
    }
    if (js == 0)
        *reinterpret_cast<float4*>(&S[((size_t)i * NH + h) * NR + rq * 4]) = acc;
}

// ---------------------------------------------------------------------------
extern "C" void kernel_launch(void* const* d_in, const int* in_sizes, int n_in,
                              void* d_out, int out_size) {
    const float* x       = (const float*)d_in[0];
    const float* symbols = (const float*)d_in[1];
    const float* fcos    = (const float*)d_in[2];
    const float* fsin    = (const float*)d_in[3];
    const float* wq_attn = (const float*)d_in[4];
    const float* wk_attn = (const float*)d_in[5];
    const float* wq_rel  = (const float*)d_in[6];
    const float* wk_rel  = (const float*)d_in[7];
    const float* wr      = (const float*)d_in[8];
    const float* wv      = (const float*)d_in[9];
    const float* wo      = (const float*)d_in[10];

    float* out  = (float*)d_out;
    float* attn = out + (size_t)L * NH * HD;
    float* rel  = attn + (size_t)NH * L * L;

    float *Q, *K, *QR, *KR, *SV, *S, *CTX, *RELT;
    cudaGetSymbolAddress((void**)&Q,  g_Q);
    cudaGetSymbolAddress((void**)&K,  g_K);
    cudaGetSymbolAddress((void**)&QR, g_QR);
    cudaGetSymbolAddress((void**)&KR, g_KR);
    cudaGetSymbolAddress((void**)&SV, g_SV);
    cudaGetSymbolAddress((void**)&S,  g_S);
    cudaGetSymbolAddress((void**)&CTX, g_CTX);
    cudaGetSymbolAddress((void**)&RELT, g_RELT);

    // 1) projections + fused RoPE (128x64 tiles — known-good config)
    proj_mma_kernel<<<dim3(4, 56), 256>>>(x, symbols, wq_attn, wq_rel, wk_rel,
                                          wk_attn, wv, fcos, fsin, Q, K, QR, KR, SV);

    // 2) fused scores + relations (3xTF32)
    scorerel_kernel<<<dim3(8, 4, 32), 256>>>(Q, K, QR, KR, attn, RELT);

    // 3) softmax
    softmax_kernel<<<NH * L, 128>>>(attn);

    // 4) fused rel transpose-out + S factorization (r-quad accumulation)
    s_trans_kernel<<<L, 256>>>(attn, RELT, rel, S);

    // 5) ctx = attn@sv (3xTF32) + S@wr
    attended3x_kernel<<<dim3(4, NH), 256>>>(attn, SV, S, wr, CTX);

    // 6) out = ctx @ wo (128x64 tiles)
    out_mma_kernel<<<dim3(4, 16), 256>>>(CTX, wo, out);
}

// round 11
// speedup vs baseline: 1.7092x; 1.0524x over previous
#include <cuda_runtime.h>
#include <cuda_bf16.h>
#include <cstdint>
#include <math.h>

#define L 512
#define Dm 1024
#define NH 16
#define NKV 4
#define NR 16
#define HD 64
#define ATTN_SCALE 0.125f
#define REL_SCALE 0.125f

// ---------------- scratch ----------------------------------------------------
__device__ float g_Q[L * NH * HD];
__device__ float g_K[L * NKV * HD];
__device__ float g_QR[L * NR * HD];
__device__ float g_KR[L * NR * HD];
__device__ float g_SV[L * NKV * HD];
__device__ float g_S[L * NH * NR];
__device__ float g_CTX[L * NH * HD];
__device__ float g_RELT[NR * L * L];   // relations in [r][i][j]

__device__ __forceinline__ float to_tf32(float x) {
    uint32_t u;
    asm("cvt.rna.tf32.f32 %0, %1;" : "=r"(u) : "f"(x));
    return __uint_as_float(u);
}
__device__ __forceinline__ void mma_tf32(float c[4], uint32_t a0, uint32_t a1,
                                         uint32_t a2, uint32_t a3,
                                         uint32_t b0, uint32_t b1) {
    asm volatile(
        "mma.sync.aligned.m16n8k8.row.col.f32.tf32.tf32.f32 "
        "{%0,%1,%2,%3}, {%4,%5,%6,%7}, {%8,%9}, {%0,%1,%2,%3};"
        : "+f"(c[0]), "+f"(c[1]), "+f"(c[2]), "+f"(c[3])
        : "r"(a0), "r"(a1), "r"(a2), "r"(a3), "r"(b0), "r"(b1));
}
__device__ __forceinline__ float2 hl_split(float x) {
    float h = to_tf32(x);
    return make_float2(h, to_tf32(x - h));
}

// ---------------- pipelined tf32 GEMM tile 128x64 (projections / out) --------
__device__ __forceinline__ void mma_gemm_tile(
    const float* __restrict__ A, int lda,
    const float* __restrict__ W, int ldb,
    float* __restrict__ C, int ldc,
    int m0, int n0, int K,
    const float* __restrict__ fcos, const float* __restrict__ fsin, int ropef)
{
    __shared__ float As[128][36];
    __shared__ float Bs[32][72];

    int tid = threadIdx.x;
    int warp = tid >> 5, lane = tid & 31;
    int tq = lane >> 2, tr = lane & 3;
    int wm = warp & 3, wn = warp >> 2;
    int mb = wm * 32, nb = wn * 32;

    float c[2][4][4];
    #pragma unroll
    for (int i = 0; i < 2; i++)
        #pragma unroll
        for (int j = 0; j < 4; j++)
            #pragma unroll
            for (int k = 0; k < 4; k++) c[i][j][k] = 0.f;

    float4 pa[4], pb[2];
    #pragma unroll
    for (int i = 0; i < 4; i++) {
        int e = tid + i * 256;
        int r = e >> 3, c4 = e & 7;
        pa[i] = *reinterpret_cast<const float4*>(&A[(size_t)(m0 + r) * lda + c4 * 4]);
    }
    #pragma unroll
    for (int i = 0; i < 2; i++) {
        int e = tid + i * 256;
        int k = e >> 4, n4 = e & 15;
        pb[i] = *reinterpret_cast<const float4*>(&W[(size_t)k * ldb + n0 + n4 * 4]);
    }

    int nch = K >> 5;
    for (int kc = 0; kc < nch; kc++) {
        #pragma unroll
        for (int i = 0; i < 4; i++) {
            int e = tid + i * 256;
            int r = e >> 3, c4 = e & 7;
            float4 v = pa[i];
            v.x = to_tf32(v.x); v.y = to_tf32(v.y); v.z = to_tf32(v.z); v.w = to_tf32(v.w);
            *reinterpret_cast<float4*>(&As[r][c4 * 4]) = v;
        }
        #pragma unroll
        for (int i = 0; i < 2; i++) {
            int e = tid + i * 256;
            int k = e >> 4, n4 = e & 15;
            float4 v = pb[i];
            v.x = to_tf32(v.x); v.y = to_tf32(v.y); v.z = to_tf32(v.z); v.w = to_tf32(v.w);
            *reinterpret_cast<float4*>(&Bs[k][n4 * 4]) = v;
        }
        __syncthreads();
        if (kc + 1 < nch) {
            int k0n = (kc + 1) << 5;
            #pragma unroll
            for (int i = 0; i < 4; i++) {
                int e = tid + i * 256;
                int r = e >> 3, c4 = e & 7;
                pa[i] = *reinterpret_cast<const float4*>(&A[(size_t)(m0 + r) * lda + k0n + c4 * 4]);
            }
            #pragma unroll
            for (int i = 0; i < 2; i++) {
                int e = tid + i * 256;
                int k = e >> 4, n4 = e & 15;
                pb[i] = *reinterpret_cast<const float4*>(&W[(size_t)(k0n + k) * ldb + n0 + n4 * 4]);
            }
        }
        #pragma unroll
        for (int ks = 0; ks < 4; ks++) {
            int kb = ks * 8;
            uint32_t a[2][4], b[4][2];
            #pragma unroll
            for (int ma = 0; ma < 2; ma++) {
                int r0 = mb + ma * 16 + tq;
                a[ma][0] = __float_as_uint(As[r0][kb + tr]);
                a[ma][1] = __float_as_uint(As[r0 + 8][kb + tr]);
                a[ma][2] = __float_as_uint(As[r0][kb + tr + 4]);
                a[ma][3] = __float_as_uint(As[r0 + 8][kb + tr + 4]);
            }
            #pragma unroll
            for (int na = 0; na < 4; na++) {
                int n_ = nb + na * 8 + tq;
                b[na][0] = __float_as_uint(Bs[kb + tr][n_]);
                b[na][1] = __float_as_uint(Bs[kb + tr + 4][n_]);
            }
            #pragma unroll
            for (int ma = 0; ma < 2; ma++)
                #pragma unroll
                for (int na = 0; na < 4; na++)
                    mma_tf32(c[ma][na], a[ma][0], a[ma][1], a[ma][2], a[ma][3],
                             b[na][0], b[na][1]);
        }
        __syncthreads();
    }

    #pragma unroll
    for (int ma = 0; ma < 2; ma++) {
        int row = m0 + mb + ma * 16 + tq;
        #pragma unroll
        for (int na = 0; na < 4; na++) {
            int col = n0 + nb + na * 8 + 2 * tr;
            float v0 = c[ma][na][0], v1 = c[ma][na][1];
            float v2 = c[ma][na][2], v3 = c[ma][na][3];
            if (ropef) {
                int p = (col & 63) >> 1;
                float c0 = fcos[row * 32 + p], s0 = fsin[row * 32 + p];
                float c1 = fcos[(row + 8) * 32 + p], s1 = fsin[(row + 8) * 32 + p];
                float t0 = v0 * c0 - v1 * s0, t1 = v0 * s0 + v1 * c0;
                float t2 = v2 * c1 - v3 * s1, t3 = v2 * s1 + v3 * c1;
                v0 = t0; v1 = t1; v2 = t2; v3 = t3;
            }
            *reinterpret_cast<float2*>(&C[(size_t)row * ldc + col]) = make_float2(v0, v1);
            *reinterpret_cast<float2*>(&C[(size_t)(row + 8) * ldc + col]) = make_float2(v2, v3);
        }
    }
}

__global__ void __launch_bounds__(256, 2) proj_mma_kernel(
    const float* __restrict__ x, const float* __restrict__ symbols,
    const float* __restrict__ wq, const float* __restrict__ wqr,
    const float* __restrict__ wkr, const float* __restrict__ wk,
    const float* __restrict__ wv,
    const float* __restrict__ fcos, const float* __restrict__ fsin,
    float* __restrict__ Q, float* __restrict__ Kp, float* __restrict__ QR,
    float* __restrict__ KR, float* __restrict__ SV)
{
    int mt = blockIdx.x;
    int t = blockIdx.y;
    const float* A = x;
    const float* W;
    float* C;
    int ldb, n0, ropef = 0;
    if (t < 16)      { W = wq;  C = Q;  ldb = 1024; n0 = t * 64; ropef = 1; }
    else if (t < 32) { W = wqr; C = QR; ldb = 1024; n0 = (t - 16) * 64; }
    else if (t < 48) { W = wkr; C = KR; ldb = 1024; n0 = (t - 32) * 64; }
    else if (t < 52) { W = wk;  C = Kp; ldb = 256;  n0 = (t - 48) * 64; ropef = 1; }
    else             { W = wv; A = symbols; C = SV; ldb = 256; n0 = (t - 52) * 64; }
    mma_gemm_tile(A, 1024, W, ldb, C, ldb, mt * 128, n0, 1024, fcos, fsin, ropef);
}

__global__ void __launch_bounds__(256, 2) out_mma_kernel(
    const float* __restrict__ CTX, const float* __restrict__ wo, float* __restrict__ out)
{
    mma_gemm_tile(CTX, 1024, wo, 1024, out, 1024, blockIdx.x * 128, blockIdx.y * 64, 1024,
                  nullptr, nullptr, 0);
}

// ---------------- 3xTF32 core: (hi,lo) packed float2 smem, pipelined ---------
template<int BNK>
__device__ __forceinline__ void mma3x_compute(
    const float* __restrict__ A, int lda,
    const float* __restrict__ B, int ldb,
    int m0, int n0, int kmax, float c[2][4][4])
{
    __shared__ float2 As[128][20];
    __shared__ float2 Bs[BNK ? 64 : 16][BNK ? 20 : 68];

    int tid = threadIdx.x;
    int warp = tid >> 5, lane = tid & 31;
    int tq = lane >> 2, tr = lane & 3;
    int wm = warp & 3, wn = warp >> 2;
    int mb = wm * 32, nb = wn * 32;

    float4 pa[2], pb;
    #pragma unroll
    for (int i = 0; i < 2; i++) {
        int e = tid + i * 256;
        int r = e >> 2, k4 = e & 3;
        pa[i] = *reinterpret_cast<const float4*>(&A[(size_t)(m0 + r) * lda + k4 * 4]);
    }
    if (BNK) {
        int r = tid >> 2, k4 = tid & 3;
        pb = *reinterpret_cast<const float4*>(&B[(size_t)(n0 + r) * ldb + k4 * 4]);
    } else {
        int k = tid >> 4, n4 = tid & 15;
        pb = *reinterpret_cast<const float4*>(&B[(size_t)k * ldb + n0 + n4 * 4]);
    }

    for (int k0 = 0; k0 < kmax; k0 += 16) {
        #pragma unroll
        for (int i = 0; i < 2; i++) {
            int e = tid + i * 256;
            int r = e >> 2, k4 = e & 3;
            float2 h0 = hl_split(pa[i].x), h1 = hl_split(pa[i].y);
            float2 h2 = hl_split(pa[i].z), h3 = hl_split(pa[i].w);
            *reinterpret_cast<float4*>(&As[r][k4 * 4]) =
                make_float4(h0.x, h0.y, h1.x, h1.y);
            *reinterpret_cast<float4*>(&As[r][k4 * 4 + 2]) =
                make_float4(h2.x, h2.y, h3.x, h3.y);
        }
        {
            float2 h0 = hl_split(pb.x), h1 = hl_split(pb.y);
            float2 h2 = hl_split(pb.z), h3 = hl_split(pb.w);
            if (BNK) {
                int r = tid >> 2, k4 = tid & 3;
                *reinterpret_cast<float4*>(&Bs[r][k4 * 4]) =
                    make_float4(h0.x, h0.y, h1.x, h1.y);
                *reinterpret_cast<float4*>(&Bs[r][k4 * 4 + 2]) =
                    make_float4(h2.x, h2.y, h3.x, h3.y);
            } else {
                int k = tid >> 4, n4 = tid & 15;
                *reinterpret_cast<float4*>(&Bs[k][n4 * 4]) =
                    make_float4(h0.x, h0.y, h1.x, h1.y);
                *reinterpret_cast<float4*>(&Bs[k][n4 * 4 + 2]) =
                    make_float4(h2.x, h2.y, h3.x, h3.y);
            }
        }
        __syncthreads();
        if (k0 + 16 < kmax) {
            int kn = k0 + 16;
            #pragma unroll
            for (int i = 0; i < 2; i++) {
                int e = tid + i * 256;
                int r = e >> 2, k4 = e & 3;
                pa[i] = *reinterpret_cast<const float4*>(&A[(size_t)(m0 + r) * lda + kn + k4 * 4]);
            }
            if (BNK) {
                int r = tid >> 2, k4 = tid & 3;
                pb = *reinterpret_cast<const float4*>(&B[(size_t)(n0 + r) * ldb + kn + k4 * 4]);
            } else {
                int k = tid >> 4, n4 = tid & 15;
                pb = *reinterpret_cast<const float4*>(&B[(size_t)(kn + k) * ldb + n0 + n4 * 4]);
            }
        }
        #pragma unroll
        for (int ks = 0; ks < 2; ks++) {
            int kb = ks * 8;
            float2 a0[2][4], b0[4][2];
            #pragma unroll
            for (int ma = 0; ma < 2; ma++) {
                int r0 = mb + ma * 16 + tq;
                a0[ma][0] = As[r0][kb + tr];
                a0[ma][1] = As[r0 + 8][kb + tr];
                a0[ma][2] = As[r0][kb + tr + 4];
                a0[ma][3] = As[r0 + 8][kb + tr + 4];
            }
            #pragma unroll
            for (int na = 0; na < 4; na++) {
                int n_ = nb + na * 8 + tq;
                if (BNK) {
                    b0[na][0] = Bs[n_][kb + tr];
                    b0[na][1] = Bs[n_][kb + tr + 4];
                } else {
                    b0[na][0] = Bs[kb + tr][n_];
                    b0[na][1] = Bs[kb + tr + 4][n_];
                }
            }
            #pragma unroll
            for (int ma = 0; ma < 2; ma++)
                #pragma unroll
                for (int na = 0; na < 4; na++) {
                    uint32_t ah0 = __float_as_uint(a0[ma][0].x), al0 = __float_as_uint(a0[ma][0].y);
                    uint32_t ah1 = __float_as_uint(a0[ma][1].x), al1 = __float_as_uint(a0[ma][1].y);
                    uint32_t ah2 = __float_as_uint(a0[ma][2].x), al2 = __float_as_uint(a0[ma][2].y);
                    uint32_t ah3 = __float_as_uint(a0[ma][3].x), al3 = __float_as_uint(a0[ma][3].y);
                    uint32_t bh0 = __float_as_uint(b0[na][0].x), bl0 = __float_as_uint(b0[na][0].y);
                    uint32_t bh1 = __float_as_uint(b0[na][1].x), bl1 = __float_as_uint(b0[na][1].y);
                    mma_tf32(c[ma][na], ah0, ah1, ah2, ah3, bl0, bl1);
                    mma_tf32(c[ma][na], al0, al1, al2, al3, bh0, bh1);
                    mma_tf32(c[ma][na], ah0, ah1, ah2, ah3, bh0, bh1);
                }
        }
        __syncthreads();
    }
}

// ---------------- fused scores + relations (3xTF32) --------------------------
__global__ void __launch_bounds__(256, 2) scorerel_kernel(
    const float* __restrict__ Q, const float* __restrict__ K,
    const float* __restrict__ QR, const float* __restrict__ KR,
    float* __restrict__ attn, float* __restrict__ relT)
{
    int z = blockIdx.z;
    int m0 = blockIdx.y * 128, n0 = blockIdx.x * 64;
    bool is_sc = (z < 16);
    if (is_sc && n0 >= m0 + 128) return;

    const float* A = is_sc ? (Q + z * HD) : (QR + (z - 16) * HD);
    const float* B = is_sc ? (K + (z >> 2) * HD) : (KR + (z - 16) * HD);
    int ldb = is_sc ? 256 : 1024;
    float* C = is_sc ? (attn + (size_t)z * L * L) : (relT + (size_t)(z - 16) * L * L);

    float c[2][4][4];
    #pragma unroll
    for (int i = 0; i < 2; i++)
        #pragma unroll
        for (int j = 0; j < 4; j++)
            #pragma unroll
            for (int k = 0; k < 4; k++) c[i][j][k] = 0.f;

    mma3x_compute<1>(A, 1024, B, ldb, m0, n0, 64, c);

    int lane = threadIdx.x & 31, warp = threadIdx.x >> 5;
    int tq = lane >> 2, tr = lane & 3;
    int mb = (warp & 3) * 32, nb = (warp >> 2) * 32;
    #pragma unroll
    for (int ma = 0; ma < 2; ma++) {
        int row = m0 + mb + ma * 16 + tq;
        #pragma unroll
        for (int na = 0; na < 4; na++) {
            int col = n0 + nb + na * 8 + 2 * tr;
            *reinterpret_cast<float2*>(&C[(size_t)row * L + col]) =
                make_float2(c[ma][na][0] * 0.125f, c[ma][na][1] * 0.125f);
            *reinterpret_cast<float2*>(&C[(size_t)(row + 8) * L + col]) =
                make_float2(c[ma][na][2] * 0.125f, c[ma][na][3] * 0.125f);
        }
    }
}

// ---------------- attended (3xTF32 attn@sv + S@wr) ---------------------------
__global__ void __launch_bounds__(256, 2) attended3x_kernel(
    const float* __restrict__ attn, const float* __restrict__ SV,
    const float* __restrict__ S, const float* __restrict__ wr,
    float* __restrict__ ctx)
{
    int h = blockIdx.y;
    int m0 = blockIdx.x * 128;
    int jmax = m0 + 128;

    float c[2][4][4];
    #pragma unroll
    for (int i = 0; i < 2; i++)
        #pragma unroll
        for (int j = 0; j < 4; j++)
            #pragma unroll
            for (int k = 0; k < 4; k++) c[i][j][k] = 0.f;

    mma3x_compute<0>(attn + (size_t)h * L * L, L, SV + (h >> 2) * HD, 256, m0, 0, jmax, c);

    __shared__ float wrs[16][64];
    __shared__ float Ss[128][17];
    int tid = threadIdx.x;
    for (int t = tid; t < 16 * 64; t += 256) {
        int rr = t >> 6, n = t & 63;
        wrs[rr][n] = wr[(size_t)rr * (NH * HD) + h * HD + n];
    }
    for (int t = tid; t < 128 * 16; t += 256) {
        int m = t >> 4, rr = t & 15;
        Ss[m][rr] = S[((size_t)(m0 + m) * NH + h) * NR + rr];
    }
    __syncthreads();

    int lane = tid & 31, warp = tid >> 5;
    int tq = lane >> 2, tr = lane & 3;
    int mb = (warp & 3) * 32, nb = (warp >> 2) * 32;
    #pragma unroll
    for (int rr = 0; rr < 16; rr++) {
        #pragma unroll
        for (int ma = 0; ma < 2; ma++) {
            float s0 = Ss[mb + ma * 16 + tq][rr];
            float s1 = Ss[mb + ma * 16 + tq + 8][rr];
            #pragma unroll
            for (int na = 0; na < 4; na++) {
                int col = nb + na * 8 + 2 * tr;
                float w0 = wrs[rr][col], w1 = wrs[rr][col + 1];
                c[ma][na][0] += s0 * w0; c[ma][na][1] += s0 * w1;
                c[ma][na][2] += s1 * w0; c[ma][na][3] += s1 * w1;
            }
        }
    }
    #pragma unroll
    for (int ma = 0; ma < 2; ma++) {
        int row = m0 + mb + ma * 16 + tq;
        #pragma unroll
        for (int na = 0; na < 4; na++) {
            int col = h * HD + nb + na * 8 + 2 * tr;
            *reinterpret_cast<float2*>(&ctx[(size_t)row * (NH * HD) + col]) =
                make_float2(c[ma][na][0], c[ma][na][1]);
            *reinterpret_cast<float2*>(&ctx[(size_t)(row + 8) * (NH * HD) + col]) =
                make_float2(c[ma][na][2], c[ma][na][3]);
        }
    }
}

// ---------------- causal softmax ---------------------------------------------
__global__ void __launch_bounds__(128) softmax_kernel(float* __restrict__ attn) {
    int row = blockIdx.x;
    int i = row & (L - 1);
    int len = i + 1;
    float4* p4 = reinterpret_cast<float4*>(attn + (size_t)row * L);
    int tid = threadIdx.x;
    int lane = tid & 31, wid = tid >> 5;
    int base = tid * 4;

    float4 v = p4[tid];
    float e0 = (base + 0 < len) ? v.x : -3.0e38f;
    float e1 = (base + 1 < len) ? v.y : -3.0e38f;
    float e2 = (base + 2 < len) ? v.z : -3.0e38f;
    float e3 = (base + 3 < len) ? v.w : -3.0e38f;

    float m = fmaxf(fmaxf(e0, e1), fmaxf(e2, e3));
    #pragma unroll
    for (int off = 16; off > 0; off >>= 1)
        m = fmaxf(m, __shfl_xor_sync(0xFFFFFFFFu, m, off));

    __shared__ float sm[8];
    if (lane == 0) sm[wid] = m;
    __syncthreads();
    m = fmaxf(fmaxf(sm[0], sm[1]), fmaxf(sm[2], sm[3]));

    float x0 = (base + 0 < len) ? __expf(e0 - m) : 0.f;
    float x1 = (base + 1 < len) ? __expf(e1 - m) : 0.f;
    float x2 = (base + 2 < len) ? __expf(e2 - m) : 0.f;
    float x3 = (base + 3 < len) ? __expf(e3 - m) : 0.f;

    float s = x0 + x1 + x2 + x3;
    #pragma unroll
    for (int off = 16; off > 0; off >>= 1)
        s += __shfl_xor_sync(0xFFFFFFFFu, s, off);
    if (lane == 0) sm[4 + wid] = s;
    __syncthreads();
    float inv = 1.f / (sm[4] + sm[5] + sm[6] + sm[7]);

    p4[tid] = make_float4(x0 * inv, x1 * inv, x2 * inv, x3 * inv);
}

// ---- fused: rel[i][j][r] transpose-write + S[i,h,r], causal chunk-skip ------
__global__ void __launch_bounds__(256) s_trans_kernel(
    const float* __restrict__ attn, const float* __restrict__ relT,
    float* __restrict__ rel, float* __restrict__ S)
{
    int i = blockIdx.x;
    int tid = threadIdx.x;
    int h = tid >> 4, r = tid & 15;
    __shared__ float attnS[16][132];
    __shared__ float relS[16][132];
    float acc = 0.f;
    for (int j0 = 0; j0 < L; j0 += 128) {
        bool do_acc = (j0 <= i);   // attn[h][i][j] == 0 for j > i
        if (do_acc) {
            #pragma unroll
            for (int e = tid; e < 512; e += 256) {
                int hh = e >> 5, q = e & 31;
                *reinterpret_cast<float4*>(&attnS[hh][q * 4]) =
                    *reinterpret_cast<const float4*>(&attn[((size_t)hh * L + i) * L + j0 + q * 4]);
            }
        }
        #pragma unroll
        for (int e = tid; e < 512; e += 256) {
            int rr = e >> 5, q = e & 31;
            *reinterpret_cast<float4*>(&relS[rr][q * 4]) =
                *reinterpret_cast<const float4*>(&relT[((size_t)rr * L + i) * L + j0 + q * 4]);
        }
        __syncthreads();
        // transposed write of the rel output (all chunks)
        #pragma unroll
        for (int e = tid; e < 512; e += 256) {
            int j = e >> 2, rq = e & 3;
            float4 v = make_float4(relS[rq * 4 + 0][j], relS[rq * 4 + 1][j],
                                   relS[rq * 4 + 2][j], relS[rq * 4 + 3][j]);
            *reinterpret_cast<float4*>(&rel[((size_t)i * L + j0 + j) * NR + rq * 4]) = v;
        }
        // S accumulation only on causal chunks (round-8 proven pattern)
        if (do_acc) {
            #pragma unroll 16
            for (int jj = 0; jj < 128; jj++)
                acc += attnS[h][jj] * relS[r][jj];
        }
        __syncthreads();
    }
    S[((size_t)i * NH + h) * NR + r] = acc;
}

// ---------------------------------------------------------------------------
extern "C" void kernel_launch(void* const* d_in, const int* in_sizes, int n_in,
                              void* d_out, int out_size) {
    const float* x       = (const float*)d_in[0];
    const float* symbols = (const float*)d_in[1];
    const float* fcos    = (const float*)d_in[2];
    const float* fsin    = (const float*)d_in[3];
    const float* wq_attn = (const float*)d_in[4];
    const float* wk_attn = (const float*)d_in[5];
    const float* wq_rel  = (const float*)d_in[6];
    const float* wk_rel  = (const float*)d_in[7];
    const float* wr      = (const float*)d_in[8];
    const float* wv      = (const float*)d_in[9];
    const float* wo      = (const float*)d_in[10];

    float* out  = (float*)d_out;
    float* attn = out + (size_t)L * NH * HD;
    float* rel  = attn + (size_t)NH * L * L;

    float *Q, *K, *QR, *KR, *SV, *S, *CTX, *RELT;
    cudaGetSymbolAddress((void**)&Q,  g_Q);
    cudaGetSymbolAddress((void**)&K,  g_K);
    cudaGetSymbolAddress((void**)&QR, g_QR);
    cudaGetSymbolAddress((void**)&KR, g_KR);
    cudaGetSymbolAddress((void**)&SV, g_SV);
    cudaGetSymbolAddress((void**)&S,  g_S);
    cudaGetSymbolAddress((void**)&CTX, g_CTX);
    cudaGetSymbolAddress((void**)&RELT, g_RELT);

    // 1) projections + fused RoPE
    proj_mma_kernel<<<dim3(4, 56), 256>>>(x, symbols, wq_attn, wq_rel, wk_rel,
                                          wk_attn, wv, fcos, fsin, Q, K, QR, KR, SV);

    // 2) fused scores + relations (3xTF32)
    scorerel_kernel<<<dim3(8, 4, 32), 256>>>(Q, K, QR, KR, attn, RELT);

    // 3) softmax
    softmax_kernel<<<NH * L, 128>>>(attn);

    // 4) fused rel transpose-out + S factorization (causal chunk-skip)
    s_trans_kernel<<<L, 256>>>(attn, RELT, rel, S);

    // 5) ctx = attn@sv (3xTF32) + S@wr
    attended3x_kernel<<<dim3(4, NH), 256>>>(attn, SV, S, wr, CTX);

    // 6) out = ctx @ wo
    out_mma_kernel<<<dim3(4, 16), 256>>>(CTX, wo, out);
}

// round 12
// speedup vs baseline: 1.7458x; 1.0214x over previous
#include <cuda_runtime.h>
#include <cuda_bf16.h>
#include <cstdint>
#include <math.h>

#define L 512
#define Dm 1024
#define NH 16
#define NKV 4
#define NR 16
#define HD 64
#define ATTN_SCALE 0.125f
#define REL_SCALE 0.125f

// ---------------- scratch ----------------------------------------------------
__device__ float g_Q[L * NH * HD];
__device__ float g_K[L * NKV * HD];
__device__ float g_QR[L * NR * HD];
__device__ float g_KR[L * NR * HD];
__device__ float g_SV[L * NKV * HD];
__device__ float g_S[L * NH * NR];
__device__ float g_S2[L * NH * NR];
__device__ float g_CTX[L * NH * HD];
__device__ float g_RELT[NR * L * L];   // relations in [r][i][j]

__device__ __forceinline__ float to_tf32(float x) {
    uint32_t u;
    asm("cvt.rna.tf32.f32 %0, %1;" : "=r"(u) : "f"(x));
    return __uint_as_float(u);
}
__device__ __forceinline__ void mma_tf32(float c[4], uint32_t a0, uint32_t a1,
                                         uint32_t a2, uint32_t a3,
                                         uint32_t b0, uint32_t b1) {
    asm volatile(
        "mma.sync.aligned.m16n8k8.row.col.f32.tf32.tf32.f32 "
        "{%0,%1,%2,%3}, {%4,%5,%6,%7}, {%8,%9}, {%0,%1,%2,%3};"
        : "+f"(c[0]), "+f"(c[1]), "+f"(c[2]), "+f"(c[3])
        : "r"(a0), "r"(a1), "r"(a2), "r"(a3), "r"(b0), "r"(b1));
}
__device__ __forceinline__ float2 hl_split(float x) {
    float h = to_tf32(x);
    return make_float2(h, to_tf32(x - h));
}

// ---------------- pipelined tf32 GEMM tile 128x64 (projections / out) --------
__device__ __forceinline__ void mma_gemm_tile(
    const float* __restrict__ A, int lda,
    const float* __restrict__ W, int ldb,
    float* __restrict__ C, int ldc,
    int m0, int n0, int K,
    const float* __restrict__ fcos, const float* __restrict__ fsin, int ropef)
{
    __shared__ float As[128][36];
    __shared__ float Bs[32][72];

    int tid = threadIdx.x;
    int warp = tid >> 5, lane = tid & 31;
    int tq = lane >> 2, tr = lane & 3;
    int wm = warp & 3, wn = warp >> 2;
    int mb = wm * 32, nb = wn * 32;

    float c[2][4][4];
    #pragma unroll
    for (int i = 0; i < 2; i++)
        #pragma unroll
        for (int j = 0; j < 4; j++)
            #pragma unroll
            for (int k = 0; k < 4; k++) c[i][j][k] = 0.f;

    float4 pa[4], pb[2];
    #pragma unroll
    for (int i = 0; i < 4; i++) {
        int e = tid + i * 256;
        int r = e >> 3, c4 = e & 7;
        pa[i] = *reinterpret_cast<const float4*>(&A[(size_t)(m0 + r) * lda + c4 * 4]);
    }
    #pragma unroll
    for (int i = 0; i < 2; i++) {
        int e = tid + i * 256;
        int k = e >> 4, n4 = e & 15;
        pb[i] = *reinterpret_cast<const float4*>(&W[(size_t)k * ldb + n0 + n4 * 4]);
    }

    int nch = K >> 5;
    for (int kc = 0; kc < nch; kc++) {
        #pragma unroll
        for (int i = 0; i < 4; i++) {
            int e = tid + i * 256;
            int r = e >> 3, c4 = e & 7;
            float4 v = pa[i];
            v.x = to_tf32(v.x); v.y = to_tf32(v.y); v.z = to_tf32(v.z); v.w = to_tf32(v.w);
            *reinterpret_cast<float4*>(&As[r][c4 * 4]) = v;
        }
        #pragma unroll
        for (int i = 0; i < 2; i++) {
            int e = tid + i * 256;
            int k = e >> 4, n4 = e & 15;
            float4 v = pb[i];
            v.x = to_tf32(v.x); v.y = to_tf32(v.y); v.z = to_tf32(v.z); v.w = to_tf32(v.w);
            *reinterpret_cast<float4*>(&Bs[k][n4 * 4]) = v;
        }
        __syncthreads();
        if (kc + 1 < nch) {
            int k0n = (kc + 1) << 5;
            #pragma unroll
            for (int i = 0; i < 4; i++) {
                int e = tid + i * 256;
                int r = e >> 3, c4 = e & 7;
                pa[i] = *reinterpret_cast<const float4*>(&A[(size_t)(m0 + r) * lda + k0n + c4 * 4]);
            }
            #pragma unroll
            for (int i = 0; i < 2; i++) {
                int e = tid + i * 256;
                int k = e >> 4, n4 = e & 15;
                pb[i] = *reinterpret_cast<const float4*>(&W[(size_t)(k0n + k) * ldb + n0 + n4 * 4]);
            }
        }
        #pragma unroll
        for (int ks = 0; ks < 4; ks++) {
            int kb = ks * 8;
            uint32_t a[2][4], b[4][2];
            #pragma unroll
            for (int ma = 0; ma < 2; ma++) {
                int r0 = mb + ma * 16 + tq;
                a[ma][0] = __float_as_uint(As[r0][kb + tr]);
                a[ma][1] = __float_as_uint(As[r0 + 8][kb + tr]);
                a[ma][2] = __float_as_uint(As[r0][kb + tr + 4]);
                a[ma][3] = __float_as_uint(As[r0 + 8][kb + tr + 4]);
            }
            #pragma unroll
            for (int na = 0; na < 4; na++) {
                int n_ = nb + na * 8 + tq;
                b[na][0] = __float_as_uint(Bs[kb + tr][n_]);
                b[na][1] = __float_as_uint(Bs[kb + tr + 4][n_]);
            }
            #pragma unroll
            for (int ma = 0; ma < 2; ma++)
                #pragma unroll
                for (int na = 0; na < 4; na++)
                    mma_tf32(c[ma][na], a[ma][0], a[ma][1], a[ma][2], a[ma][3],
                             b[na][0], b[na][1]);
        }
        __syncthreads();
    }

    #pragma unroll
    for (int ma = 0; ma < 2; ma++) {
        int row = m0 + mb + ma * 16 + tq;
        #pragma unroll
        for (int na = 0; na < 4; na++) {
            int col = n0 + nb + na * 8 + 2 * tr;
            float v0 = c[ma][na][0], v1 = c[ma][na][1];
            float v2 = c[ma][na][2], v3 = c[ma][na][3];
            if (ropef) {
                int p = (col & 63) >> 1;
                float c0 = fcos[row * 32 + p], s0 = fsin[row * 32 + p];
                float c1 = fcos[(row + 8) * 32 + p], s1 = fsin[(row + 8) * 32 + p];
                float t0 = v0 * c0 - v1 * s0, t1 = v0 * s0 + v1 * c0;
                float t2 = v2 * c1 - v3 * s1, t3 = v2 * s1 + v3 * c1;
                v0 = t0; v1 = t1; v2 = t2; v3 = t3;
            }
            *reinterpret_cast<float2*>(&C[(size_t)row * ldc + col]) = make_float2(v0, v1);
            *reinterpret_cast<float2*>(&C[(size_t)(row + 8) * ldc + col]) = make_float2(v2, v3);
        }
    }
}

__global__ void __launch_bounds__(256, 2) proj_mma_kernel(
    const float* __restrict__ x, const float* __restrict__ symbols,
    const float* __restrict__ wq, const float* __restrict__ wqr,
    const float* __restrict__ wkr, const float* __restrict__ wk,
    const float* __restrict__ wv,
    const float* __restrict__ fcos, const float* __restrict__ fsin,
    float* __restrict__ Q, float* __restrict__ Kp, float* __restrict__ QR,
    float* __restrict__ KR, float* __restrict__ SV)
{
    int mt = blockIdx.x;
    int t = blockIdx.y;
    const float* A = x;
    const float* W;
    float* C;
    int ldb, n0, ropef = 0;
    if (t < 16)      { W = wq;  C = Q;  ldb = 1024; n0 = t * 64; ropef = 1; }
    else if (t < 32) { W = wqr; C = QR; ldb = 1024; n0 = (t - 16) * 64; }
    else if (t < 48) { W = wkr; C = KR; ldb = 1024; n0 = (t - 32) * 64; }
    else if (t < 52) { W = wk;  C = Kp; ldb = 256;  n0 = (t - 48) * 64; ropef = 1; }
    else             { W = wv; A = symbols; C = SV; ldb = 256; n0 = (t - 52) * 64; }
    mma_gemm_tile(A, 1024, W, ldb, C, ldb, mt * 128, n0, 1024, fcos, fsin, ropef);
}

__global__ void __launch_bounds__(256, 2) out_mma_kernel(
    const float* __restrict__ CTX, const float* __restrict__ wo, float* __restrict__ out)
{
    mma_gemm_tile(CTX, 1024, wo, 1024, out, 1024, blockIdx.x * 128, blockIdx.y * 64, 1024,
                  nullptr, nullptr, 0);
}

// ---------------- 3xTF32 core: (hi,lo) packed float2 smem, pipelined ---------
template<int BNK>
__device__ __forceinline__ void mma3x_compute(
    const float* __restrict__ A, int lda,
    const float* __restrict__ B, int ldb,
    int m0, int n0, int kmax, float c[2][4][4])
{
    __shared__ float2 As[128][20];
    __shared__ float2 Bs[BNK ? 64 : 16][BNK ? 20 : 68];

    int tid = threadIdx.x;
    int warp = tid >> 5, lane = tid & 31;
    int tq = lane >> 2, tr = lane & 3;
    int wm = warp & 3, wn = warp >> 2;
    int mb = wm * 32, nb = wn * 32;

    float4 pa[2], pb;
    #pragma unroll
    for (int i = 0; i < 2; i++) {
        int e = tid + i * 256;
        int r = e >> 2, k4 = e & 3;
        pa[i] = *reinterpret_cast<const float4*>(&A[(size_t)(m0 + r) * lda + k4 * 4]);
    }
    if (BNK) {
        int r = tid >> 2, k4 = tid & 3;
        pb = *reinterpret_cast<const float4*>(&B[(size_t)(n0 + r) * ldb + k4 * 4]);
    } else {
        int k = tid >> 4, n4 = tid & 15;
        pb = *reinterpret_cast<const float4*>(&B[(size_t)k * ldb + n0 + n4 * 4]);
    }

    for (int k0 = 0; k0 < kmax; k0 += 16) {
        #pragma unroll
        for (int i = 0; i < 2; i++) {
            int e = tid + i * 256;
            int r = e >> 2, k4 = e & 3;
            float2 h0 = hl_split(pa[i].x), h1 = hl_split(pa[i].y);
            float2 h2 = hl_split(pa[i].z), h3 = hl_split(pa[i].w);
            *reinterpret_cast<float4*>(&As[r][k4 * 4]) =
                make_float4(h0.x, h0.y, h1.x, h1.y);
            *reinterpret_cast<float4*>(&As[r][k4 * 4 + 2]) =
                make_float4(h2.x, h2.y, h3.x, h3.y);
        }
        {
            float2 h0 = hl_split(pb.x), h1 = hl_split(pb.y);
            float2 h2 = hl_split(pb.z), h3 = hl_split(pb.w);
            if (BNK) {
                int r = tid >> 2, k4 = tid & 3;
                *reinterpret_cast<float4*>(&Bs[r][k4 * 4]) =
                    make_float4(h0.x, h0.y, h1.x, h1.y);
                *reinterpret_cast<float4*>(&Bs[r][k4 * 4 + 2]) =
                    make_float4(h2.x, h2.y, h3.x, h3.y);
            } else {
                int k = tid >> 4, n4 = tid & 15;
                *reinterpret_cast<float4*>(&Bs[k][n4 * 4]) =
                    make_float4(h0.x, h0.y, h1.x, h1.y);
                *reinterpret_cast<float4*>(&Bs[k][n4 * 4 + 2]) =
                    make_float4(h2.x, h2.y, h3.x, h3.y);
            }
        }
        __syncthreads();
        if (k0 + 16 < kmax) {
            int kn = k0 + 16;
            #pragma unroll
            for (int i = 0; i < 2; i++) {
                int e = tid + i * 256;
                int r = e >> 2, k4 = e & 3;
                pa[i] = *reinterpret_cast<const float4*>(&A[(size_t)(m0 + r) * lda + kn + k4 * 4]);
            }
            if (BNK) {
                int r = tid >> 2, k4 = tid & 3;
                pb = *reinterpret_cast<const float4*>(&B[(size_t)(n0 + r) * ldb + kn + k4 * 4]);
            } else {
                int k = tid >> 4, n4 = tid & 15;
                pb = *reinterpret_cast<const float4*>(&B[(size_t)(kn + k) * ldb + n0 + n4 * 4]);
            }
        }
        #pragma unroll
        for (int ks = 0; ks < 2; ks++) {
            int kb = ks * 8;
            float2 a0[2][4], b0[4][2];
            #pragma unroll
            for (int ma = 0; ma < 2; ma++) {
                int r0 = mb + ma * 16 + tq;
                a0[ma][0] = As[r0][kb + tr];
                a0[ma][1] = As[r0 + 8][kb + tr];
                a0[ma][2] = As[r0][kb + tr + 4];
                a0[ma][3] = As[r0 + 8][kb + tr + 4];
            }
            #pragma unroll
            for (int na = 0; na < 4; na++) {
                int n_ = nb + na * 8 + tq;
                if (BNK) {
                    b0[na][0] = Bs[n_][kb + tr];
                    b0[na][1] = Bs[n_][kb + tr + 4];
                } else {
                    b0[na][0] = Bs[kb + tr][n_];
                    b0[na][1] = Bs[kb + tr + 4][n_];
                }
            }
            #pragma unroll
            for (int ma = 0; ma < 2; ma++)
                #pragma unroll
                for (int na = 0; na < 4; na++) {
                    uint32_t ah0 = __float_as_uint(a0[ma][0].x), al0 = __float_as_uint(a0[ma][0].y);
                    uint32_t ah1 = __float_as_uint(a0[ma][1].x), al1 = __float_as_uint(a0[ma][1].y);
                    uint32_t ah2 = __float_as_uint(a0[ma][2].x), al2 = __float_as_uint(a0[ma][2].y);
                    uint32_t ah3 = __float_as_uint(a0[ma][3].x), al3 = __float_as_uint(a0[ma][3].y);
                    uint32_t bh0 = __float_as_uint(b0[na][0].x), bl0 = __float_as_uint(b0[na][0].y);
                    uint32_t bh1 = __float_as_uint(b0[na][1].x), bl1 = __float_as_uint(b0[na][1].y);
                    mma_tf32(c[ma][na], ah0, ah1, ah2, ah3, bl0, bl1);
                    mma_tf32(c[ma][na], al0, al1, al2, al3, bh0, bh1);
                    mma_tf32(c[ma][na], ah0, ah1, ah2, ah3, bh0, bh1);
                }
        }
        __syncthreads();
    }
}

// ---------------- fused scores + relations (3xTF32) --------------------------
__global__ void __launch_bounds__(256, 2) scorerel_kernel(
    const float* __restrict__ Q, const float* __restrict__ K,
    const float* __restrict__ QR, const float* __restrict__ KR,
    float* __restrict__ attn, float* __restrict__ relT)
{
    int z = blockIdx.z;
    int m0 = blockIdx.y * 128, n0 = blockIdx.x * 64;
    bool is_sc = (z < 16);
    if (is_sc && n0 >= m0 + 128) return;

    const float* A = is_sc ? (Q + z * HD) : (QR + (z - 16) * HD);
    const float* B = is_sc ? (K + (z >> 2) * HD) : (KR + (z - 16) * HD);
    int ldb = is_sc ? 256 : 1024;
    float* C = is_sc ? (attn + (size_t)z * L * L) : (relT + (size_t)(z - 16) * L * L);

    float c[2][4][4];
    #pragma unroll
    for (int i = 0; i < 2; i++)
        #pragma unroll
        for (int j = 0; j < 4; j++)
            #pragma unroll
            for (int k = 0; k < 4; k++) c[i][j][k] = 0.f;

    mma3x_compute<1>(A, 1024, B, ldb, m0, n0, 64, c);

    int lane = threadIdx.x & 31, warp = threadIdx.x >> 5;
    int tq = lane >> 2, tr = lane & 3;
    int mb = (warp & 3) * 32, nb = (warp >> 2) * 32;
    #pragma unroll
    for (int ma = 0; ma < 2; ma++) {
        int row = m0 + mb + ma * 16 + tq;
        #pragma unroll
        for (int na = 0; na < 4; na++) {
            int col = n0 + nb + na * 8 + 2 * tr;
            *reinterpret_cast<float2*>(&C[(size_t)row * L + col]) =
                make_float2(c[ma][na][0] * 0.125f, c[ma][na][1] * 0.125f);
            *reinterpret_cast<float2*>(&C[(size_t)(row + 8) * L + col]) =
                make_float2(c[ma][na][2] * 0.125f, c[ma][na][3] * 0.125f);
        }
    }
}

// ---------------- attended (3xTF32 attn@sv + (S+S2)@wr) ----------------------
__global__ void __launch_bounds__(256, 2) attended3x_kernel(
    const float* __restrict__ attn, const float* __restrict__ SV,
    const float* __restrict__ S, const float* __restrict__ S2,
    const float* __restrict__ wr, float* __restrict__ ctx)
{
    int h = blockIdx.y;
    int m0 = blockIdx.x * 128;
    int jmax = m0 + 128;

    float c[2][4][4];
    #pragma unroll
    for (int i = 0; i < 2; i++)
        #pragma unroll
        for (int j = 0; j < 4; j++)
            #pragma unroll
            for (int k = 0; k < 4; k++) c[i][j][k] = 0.f;

    mma3x_compute<0>(attn + (size_t)h * L * L, L, SV + (h >> 2) * HD, 256, m0, 0, jmax, c);

    __shared__ float wrs[16][64];
    __shared__ float Ss[128][17];
    int tid = threadIdx.x;
    for (int t = tid; t < 16 * 64; t += 256) {
        int rr = t >> 6, n = t & 63;
        wrs[rr][n] = wr[(size_t)rr * (NH * HD) + h * HD + n];
    }
    for (int t = tid; t < 128 * 16; t += 256) {
        int m = t >> 4, rr = t & 15;
        size_t idx = ((size_t)(m0 + m) * NH + h) * NR + rr;
        Ss[m][rr] = S[idx] + S2[idx];
    }
    __syncthreads();

    int lane = tid & 31, warp = tid >> 5;
    int tq = lane >> 2, tr = lane & 3;
    int mb = (warp & 3) * 32, nb = (warp >> 2) * 32;
    #pragma unroll
    for (int rr = 0; rr < 16; rr++) {
        #pragma unroll
        for (int ma = 0; ma < 2; ma++) {
            float s0 = Ss[mb + ma * 16 + tq][rr];
            float s1 = Ss[mb + ma * 16 + tq + 8][rr];
            #pragma unroll
            for (int na = 0; na < 4; na++) {
                int col = nb + na * 8 + 2 * tr;
                float w0 = wrs[rr][col], w1 = wrs[rr][col + 1];
                c[ma][na][0] += s0 * w0; c[ma][na][1] += s0 * w1;
                c[ma][na][2] += s1 * w0; c[ma][na][3] += s1 * w1;
            }
        }
    }
    #pragma unroll
    for (int ma = 0; ma < 2; ma++) {
        int row = m0 + mb + ma * 16 + tq;
        #pragma unroll
        for (int na = 0; na < 4; na++) {
            int col = h * HD + nb + na * 8 + 2 * tr;
            *reinterpret_cast<float2*>(&ctx[(size_t)row * (NH * HD) + col]) =
                make_float2(c[ma][na][0], c[ma][na][1]);
            *reinterpret_cast<float2*>(&ctx[(size_t)(row + 8) * (NH * HD) + col]) =
                make_float2(c[ma][na][2], c[ma][na][3]);
        }
    }
}

// ---------------- causal softmax ---------------------------------------------
__global__ void __launch_bounds__(128) softmax_kernel(float* __restrict__ attn) {
    int row = blockIdx.x;
    int i = row & (L - 1);
    int len = i + 1;
    float4* p4 = reinterpret_cast<float4*>(attn + (size_t)row * L);
    int tid = threadIdx.x;
    int lane = tid & 31, wid = tid >> 5;
    int base = tid * 4;

    float4 v = p4[tid];
    float e0 = (base + 0 < len) ? v.x : -3.0e38f;
    float e1 = (base + 1 < len) ? v.y : -3.0e38f;
    float e2 = (base + 2 < len) ? v.z : -3.0e38f;
    float e3 = (base + 3 < len) ? v.w : -3.0e38f;

    float m = fmaxf(fmaxf(e0, e1), fmaxf(e2, e3));
    #pragma unroll
    for (int off = 16; off > 0; off >>= 1)
        m = fmaxf(m, __shfl_xor_sync(0xFFFFFFFFu, m, off));

    __shared__ float sm[8];
    if (lane == 0) sm[wid] = m;
    __syncthreads();
    m = fmaxf(fmaxf(sm[0], sm[1]), fmaxf(sm[2], sm[3]));

    float x0 = (base + 0 < len) ? __expf(e0 - m) : 0.f;
    float x1 = (base + 1 < len) ? __expf(e1 - m) : 0.f;
    float x2 = (base + 2 < len) ? __expf(e2 - m) : 0.f;
    float x3 = (base + 3 < len) ? __expf(e3 - m) : 0.f;

    float s = x0 + x1 + x2 + x3;
    #pragma unroll
    for (int off = 16; off > 0; off >>= 1)
        s += __shfl_xor_sync(0xFFFFFFFFu, s, off);
    if (lane == 0) sm[4 + wid] = s;
    __syncthreads();
    float inv = 1.f / (sm[4] + sm[5] + sm[6] + sm[7]);

    p4[tid] = make_float4(x0 * inv, x1 * inv, x2 * inv, x3 * inv);
}

// ---- fused: rel transpose-write + partial S, split over j-halves ------------
// grid (L, 2): block (i, jh) handles chunks j0 = jh*256, jh*256+128.
__global__ void __launch_bounds__(256) s_trans_kernel(
    const float* __restrict__ attn, const float* __restrict__ relT,
    float* __restrict__ rel, float* __restrict__ S, float* __restrict__ S2)
{
    int i = blockIdx.x;
    int jh = blockIdx.y;
    int tid = threadIdx.x;
    int h = tid >> 4, r = tid & 15;
    __shared__ float attnS[16][132];
    __shared__ float relS[16][132];
    float acc = 0.f;
    int jbeg = jh * 256;
    for (int j0 = jbeg; j0 < jbeg + 256; j0 += 128) {
        bool do_acc = (j0 <= i);   // attn[h][i][j] == 0 for j > i
        if (do_acc) {
            #pragma unroll
            for (int e = tid; e < 512; e += 256) {
                int hh = e >> 5, q = e & 31;
                *reinterpret_cast<float4*>(&attnS[hh][q * 4]) =
                    *reinterpret_cast<const float4*>(&attn[((size_t)hh * L + i) * L + j0 + q * 4]);
            }
        }
        #pragma unroll
        for (int e = tid; e < 512; e += 256) {
            int rr = e >> 5, q = e & 31;
            *reinterpret_cast<float4*>(&relS[rr][q * 4]) =
                *reinterpret_cast<const float4*>(&relT[((size_t)rr * L + i) * L + j0 + q * 4]);
        }
        __syncthreads();
        // transposed write of the rel output (all chunks)
        #pragma unroll
        for (int e = tid; e < 512; e += 256) {
            int j = e >> 2, rq = e & 3;
            float4 v = make_float4(relS[rq * 4 + 0][j], relS[rq * 4 + 1][j],
                                   relS[rq * 4 + 2][j], relS[rq * 4 + 3][j]);
            *reinterpret_cast<float4*>(&rel[((size_t)i * L + j0 + j) * NR + rq * 4]) = v;
        }
        if (do_acc) {
            #pragma unroll 16
            for (int jj = 0; jj < 128; jj++)
                acc += attnS[h][jj] * relS[r][jj];
        }
        __syncthreads();
    }
    float* So = jh ? S2 : S;
    So[((size_t)i * NH + h) * NR + r] = acc;
}

// ---------------------------------------------------------------------------
extern "C" void kernel_launch(void* const* d_in, const int* in_sizes, int n_in,
                              void* d_out, int out_size) {
    const float* x       = (const float*)d_in[0];
    const float* symbols = (const float*)d_in[1];
    const float* fcos    = (const float*)d_in[2];
    const float* fsin    = (const float*)d_in[3];
    const float* wq_attn = (const float*)d_in[4];
    const float* wk_attn = (const float*)d_in[5];
    const float* wq_rel  = (const float*)d_in[6];
    const float* wk_rel  = (const float*)d_in[7];
    const float* wr      = (const float*)d_in[8];
    const float* wv      = (const float*)d_in[9];
    const float* wo      = (const float*)d_in[10];

    float* out  = (float*)d_out;
    float* attn = out + (size_t)L * NH * HD;
    float* rel  = attn + (size_t)NH * L * L;

    float *Q, *K, *QR, *KR, *SV, *S, *S2, *CTX, *RELT;
    cudaGetSymbolAddress((void**)&Q,  g_Q);
    cudaGetSymbolAddress((void**)&K,  g_K);
    cudaGetSymbolAddress((void**)&QR, g_QR);
    cudaGetSymbolAddress((void**)&KR, g_KR);
    cudaGetSymbolAddress((void**)&SV, g_SV);
    cudaGetSymbolAddress((void**)&S,  g_S);
    cudaGetSymbolAddress((void**)&S2, g_S2);
    cudaGetSymbolAddress((void**)&CTX, g_CTX);
    cudaGetSymbolAddress((void**)&RELT, g_RELT);

    // 1) projections + fused RoPE
    proj_mma_kernel<<<dim3(4, 56), 256>>>(x, symbols, wq_attn, wq_rel, wk_rel,
                                          wk_attn, wv, fcos, fsin, Q, K, QR, KR, SV);

    // 2) fused scores + relations (3xTF32)
    scorerel_kernel<<<dim3(8, 4, 32), 256>>>(Q, K, QR, KR, attn, RELT);

    // 3) softmax
    softmax_kernel<<<NH * L, 128>>>(attn);

    // 4) fused rel transpose-out + partial S, j-split for 2x parallelism
    s_trans_kernel<<<dim3(L, 2), 256>>>(attn, RELT, rel, S, S2);

    // 5) ctx = attn@sv (3xTF32) + (S+S2)@wr
    attended3x_kernel<<<dim3(4, NH), 256>>>(attn, SV, S, S2, wr, CTX);

    // 6) out = ctx @ wo
    out_mma_kernel<<<dim3(4, 16), 256>>>(CTX, wo, out);
}

// round 13
// speedup vs baseline: 1.7528x; 1.0041x over previous
#include <cuda_runtime.h>
#include <cuda_bf16.h>
#include <cstdint>
#include <math.h>

#define L 512
#define Dm 1024
#define NH 16
#define NKV 4
#define NR 16
#define HD 64
#define ATTN_SCALE 0.125f
#define REL_SCALE 0.125f

// ---------------- scratch ----------------------------------------------------
__device__ float g_Q[L * NH * HD];
__device__ float g_K[L * NKV * HD];
__device__ float g_QR[L * NR * HD];
__device__ float g_KR[L * NR * HD];
__device__ float g_SV[L * NKV * HD];
__device__ float g_S[L * NH * NR];
__device__ float g_S2[L * NH * NR];
__device__ float g_CTX[L * NH * HD];
__device__ float g_RELT[NR * L * L];   // relations in [r][i][j]

__device__ __forceinline__ float to_tf32(float x) {
    uint32_t u;
    asm("cvt.rna.tf32.f32 %0, %1;" : "=r"(u) : "f"(x));
    return __uint_as_float(u);
}
__device__ __forceinline__ void mma_tf32(float c[4], uint32_t a0, uint32_t a1,
                                         uint32_t a2, uint32_t a3,
                                         uint32_t b0, uint32_t b1) {
    asm volatile(
        "mma.sync.aligned.m16n8k8.row.col.f32.tf32.tf32.f32 "
        "{%0,%1,%2,%3}, {%4,%5,%6,%7}, {%8,%9}, {%0,%1,%2,%3};"
        : "+f"(c[0]), "+f"(c[1]), "+f"(c[2]), "+f"(c[3])
        : "r"(a0), "r"(a1), "r"(a2), "r"(a3), "r"(b0), "r"(b1));
}
__device__ __forceinline__ float2 hl_split(float x) {
    float h = to_tf32(x);
    return make_float2(h, to_tf32(x - h));
}

// ---- single-pass tf32 GEMM tile 128x64, DOUBLE-BUFFERED smem (K=16 chunks) --
// Optional fused RoPE; optional S@wr epilogue (attended path).
__device__ __forceinline__ void mma_gemm_tile(
    const float* __restrict__ A, int lda,
    const float* __restrict__ W, int ldb,
    float* __restrict__ C, int ldc,
    int m0, int n0, int K,
    const float* __restrict__ fcos, const float* __restrict__ fsin, int ropef,
    const float* __restrict__ Sa, const float* __restrict__ Sb,
    const float* __restrict__ wrp, int hcol)
{
    __shared__ float As[2][128][20];   // [buf][m][k]
    __shared__ float Bs[2][16][72];    // [buf][k][n]

    int tid = threadIdx.x;
    int warp = tid >> 5, lane = tid & 31;
    int tq = lane >> 2, tr = lane & 3;
    int wm = warp & 3, wn = warp >> 2;
    int mb = wm * 32, nb = wn * 32;

    float c[2][4][4];
    #pragma unroll
    for (int i = 0; i < 2; i++)
        #pragma unroll
        for (int j = 0; j < 4; j++)
            #pragma unroll
            for (int k = 0; k < 4; k++) c[i][j][k] = 0.f;

    // per-thread load coords
    int ar0 = tid >> 2, ak4 = tid & 3;         // A: +i*64 rows
    int bk = tid >> 4, bn4 = tid & 15;         // B

    float4 pa[2], pb;
    #pragma unroll
    for (int i = 0; i < 2; i++)
        pa[i] = *reinterpret_cast<const float4*>(
            &A[(size_t)(m0 + ar0 + i * 64) * lda + ak4 * 4]);
    pb = *reinterpret_cast<const float4*>(&W[(size_t)bk * ldb + n0 + bn4 * 4]);

    int nch = K >> 4;
    for (int kc = 0; kc < nch; kc++) {
        int buf = kc & 1;
        #pragma unroll
        for (int i = 0; i < 2; i++) {
            float4 v = pa[i];
            v.x = to_tf32(v.x); v.y = to_tf32(v.y); v.z = to_tf32(v.z); v.w = to_tf32(v.w);
            *reinterpret_cast<float4*>(&As[buf][ar0 + i * 64][ak4 * 4]) = v;
        }
        {
            float4 v = pb;
            v.x = to_tf32(v.x); v.y = to_tf32(v.y); v.z = to_tf32(v.z); v.w = to_tf32(v.w);
            *reinterpret_cast<float4*>(&Bs[buf][bk][bn4 * 4]) = v;
        }
        __syncthreads();
        if (kc + 1 < nch) {
            int k0n = (kc + 1) << 4;
            #pragma unroll
            for (int i = 0; i < 2; i++)
                pa[i] = *reinterpret_cast<const float4*>(
                    &A[(size_t)(m0 + ar0 + i * 64) * lda + k0n + ak4 * 4]);
            pb = *reinterpret_cast<const float4*>(&W[(size_t)(k0n + bk) * ldb + n0 + bn4 * 4]);
        }
        #pragma unroll
        for (int ks = 0; ks < 2; ks++) {
            int kb = ks * 8;
            uint32_t a[2][4], b[4][2];
            #pragma unroll
            for (int ma = 0; ma < 2; ma++) {
                int r0 = mb + ma * 16 + tq;
                a[ma][0] = __float_as_uint(As[buf][r0][kb + tr]);
                a[ma][1] = __float_as_uint(As[buf][r0 + 8][kb + tr]);
                a[ma][2] = __float_as_uint(As[buf][r0][kb + tr + 4]);
                a[ma][3] = __float_as_uint(As[buf][r0 + 8][kb + tr + 4]);
            }
            #pragma unroll
            for (int na = 0; na < 4; na++) {
                int n_ = nb + na * 8 + tq;
                b[na][0] = __float_as_uint(Bs[buf][kb + tr][n_]);
                b[na][1] = __float_as_uint(Bs[buf][kb + tr + 4][n_]);
            }
            #pragma unroll
            for (int ma = 0; ma < 2; ma++)
                #pragma unroll
                for (int na = 0; na < 4; na++)
                    mma_tf32(c[ma][na], a[ma][0], a[ma][1], a[ma][2], a[ma][3],
                             b[na][0], b[na][1]);
        }
        // no trailing sync: next iter writes the other buffer
    }

    // optional S@wr epilogue (attended): repurpose smem after all MMAs done
    if (Sa) {
        __syncthreads();
        float (*Ss)[17] = reinterpret_cast<float(*)[17]>(&As[0][0][0]);
        float (*wrs)[64] = reinterpret_cast<float(*)[64]>(&Bs[0][0][0]);
        int h = hcol >> 6;
        for (int t = tid; t < 16 * 64; t += 256)
            wrs[t >> 6][t & 63] = wrp[(size_t)(t >> 6) * (NH * HD) + hcol + (t & 63)];
        for (int t = tid; t < 128 * 16; t += 256) {
            int m = t >> 4, rr = t & 15;
            size_t idx = ((size_t)(m0 + m) * NH + h) * NR + rr;
            Ss[m][rr] = Sa[idx] + Sb[idx];
        }
        __syncthreads();
        #pragma unroll
        for (int rr = 0; rr < 16; rr++) {
            #pragma unroll
            for (int ma = 0; ma < 2; ma++) {
                float s0 = Ss[mb + ma * 16 + tq][rr];
                float s1 = Ss[mb + ma * 16 + tq + 8][rr];
                #pragma unroll
                for (int na = 0; na < 4; na++) {
                    int col = nb + na * 8 + 2 * tr;
                    float w0 = wrs[rr][col], w1 = wrs[rr][col + 1];
                    c[ma][na][0] += s0 * w0; c[ma][na][1] += s0 * w1;
                    c[ma][na][2] += s1 * w0; c[ma][na][3] += s1 * w1;
                }
            }
        }
    }

    #pragma unroll
    for (int ma = 0; ma < 2; ma++) {
        int row = m0 + mb + ma * 16 + tq;
        #pragma unroll
        for (int na = 0; na < 4; na++) {
            int col = n0 + nb + na * 8 + 2 * tr;
            float v0 = c[ma][na][0], v1 = c[ma][na][1];
            float v2 = c[ma][na][2], v3 = c[ma][na][3];
            if (ropef) {
                int p = (col & 63) >> 1;
                float c0 = fcos[row * 32 + p], s0 = fsin[row * 32 + p];
                float c1 = fcos[(row + 8) * 32 + p], s1 = fsin[(row + 8) * 32 + p];
                float t0 = v0 * c0 - v1 * s0, t1 = v0 * s0 + v1 * c0;
                float t2 = v2 * c1 - v3 * s1, t3 = v2 * s1 + v3 * c1;
                v0 = t0; v1 = t1; v2 = t2; v3 = t3;
            }
            *reinterpret_cast<float2*>(&C[(size_t)row * ldc + col]) = make_float2(v0, v1);
            *reinterpret_cast<float2*>(&C[(size_t)(row + 8) * ldc + col]) = make_float2(v2, v3);
        }
    }
}

__global__ void __launch_bounds__(256, 2) proj_mma_kernel(
    const float* __restrict__ x, const float* __restrict__ symbols,
    const float* __restrict__ wq, const float* __restrict__ wqr,
    const float* __restrict__ wkr, const float* __restrict__ wk,
    const float* __restrict__ wv,
    const float* __restrict__ fcos, const float* __restrict__ fsin,
    float* __restrict__ Q, float* __restrict__ Kp, float* __restrict__ QR,
    float* __restrict__ KR, float* __restrict__ SV)
{
    int mt = blockIdx.x;
    int t = blockIdx.y;
    const float* A = x;
    const float* W;
    float* C;
    int ldb, n0, ropef = 0;
    if (t < 16)      { W = wq;  C = Q;  ldb = 1024; n0 = t * 64; ropef = 1; }
    else if (t < 32) { W = wqr; C = QR; ldb = 1024; n0 = (t - 16) * 64; }
    else if (t < 48) { W = wkr; C = KR; ldb = 1024; n0 = (t - 32) * 64; }
    else if (t < 52) { W = wk;  C = Kp; ldb = 256;  n0 = (t - 48) * 64; ropef = 1; }
    else             { W = wv; A = symbols; C = SV; ldb = 256; n0 = (t - 52) * 64; }
    mma_gemm_tile(A, 1024, W, ldb, C, ldb, mt * 128, n0, 1024, fcos, fsin, ropef,
                  nullptr, nullptr, nullptr, 0);
}

__global__ void __launch_bounds__(256, 2) out_mma_kernel(
    const float* __restrict__ CTX, const float* __restrict__ wo, float* __restrict__ out)
{
    mma_gemm_tile(CTX, 1024, wo, 1024, out, 1024, blockIdx.x * 128, blockIdx.y * 64, 1024,
                  nullptr, nullptr, 0, nullptr, nullptr, nullptr, 0);
}

// ---------------- attended: single-pass tf32 attn@sv + S@wr epilogue ---------
__global__ void __launch_bounds__(256, 2) attended_kernel(
    const float* __restrict__ attn, const float* __restrict__ SV,
    const float* __restrict__ S, const float* __restrict__ S2,
    const float* __restrict__ wr, float* __restrict__ ctx)
{
    int h = blockIdx.y;
    int m0 = blockIdx.x * 128;
    int jmax = m0 + 128;   // causal: attn zero beyond diagonal
    mma_gemm_tile(attn + (size_t)h * L * L, L, SV + (h >> 2) * HD, NKV * HD,
                  ctx + h * HD, NH * HD, m0, 0, jmax,
                  nullptr, nullptr, 0, S, S2, wr, h * HD);
}

// ---------------- 3xTF32 core (scores/relations; BNK=1 only) -----------------
__device__ __forceinline__ void mma3x_compute(
    const float* __restrict__ A, int lda,
    const float* __restrict__ B, int ldb,
    int m0, int n0, int kmax, float c[2][4][4])
{
    __shared__ float2 As[128][20];
    __shared__ float2 Bs[64][20];

    int tid = threadIdx.x;
    int warp = tid >> 5, lane = tid & 31;
    int tq = lane >> 2, tr = lane & 3;
    int wm = warp & 3, wn = warp >> 2;
    int mb = wm * 32, nb = wn * 32;

    float4 pa[2], pb;
    #pragma unroll
    for (int i = 0; i < 2; i++) {
        int e = tid + i * 256;
        int r = e >> 2, k4 = e & 3;
        pa[i] = *reinterpret_cast<const float4*>(&A[(size_t)(m0 + r) * lda + k4 * 4]);
    }
    {
        int r = tid >> 2, k4 = tid & 3;
        pb = *reinterpret_cast<const float4*>(&B[(size_t)(n0 + r) * ldb + k4 * 4]);
    }

    for (int k0 = 0; k0 < kmax; k0 += 16) {
        #pragma unroll
        for (int i = 0; i < 2; i++) {
            int e = tid + i * 256;
            int r = e >> 2, k4 = e & 3;
            float2 h0 = hl_split(pa[i].x), h1 = hl_split(pa[i].y);
            float2 h2 = hl_split(pa[i].z), h3 = hl_split(pa[i].w);
            *reinterpret_cast<float4*>(&As[r][k4 * 4]) =
                make_float4(h0.x, h0.y, h1.x, h1.y);
            *reinterpret_cast<float4*>(&As[r][k4 * 4 + 2]) =
                make_float4(h2.x, h2.y, h3.x, h3.y);
        }
        {
            int r = tid >> 2, k4 = tid & 3;
            float2 h0 = hl_split(pb.x), h1 = hl_split(pb.y);
            float2 h2 = hl_split(pb.z), h3 = hl_split(pb.w);
            *reinterpret_cast<float4*>(&Bs[r][k4 * 4]) =
                make_float4(h0.x, h0.y, h1.x, h1.y);
            *reinterpret_cast<float4*>(&Bs[r][k4 * 4 + 2]) =
                make_float4(h2.x, h2.y, h3.x, h3.y);
        }
        __syncthreads();
        if (k0 + 16 < kmax) {
            int kn = k0 + 16;
            #pragma unroll
            for (int i = 0; i < 2; i++) {
                int e = tid + i * 256;
                int r = e >> 2, k4 = e & 3;
                pa[i] = *reinterpret_cast<const float4*>(&A[(size_t)(m0 + r) * lda + kn + k4 * 4]);
            }
            {
                int r = tid >> 2, k4 = tid & 3;
                pb = *reinterpret_cast<const float4*>(&B[(size_t)(n0 + r) * ldb + kn + k4 * 4]);
            }
        }
        #pragma unroll
        for (int ks = 0; ks < 2; ks++) {
            int kb = ks * 8;
            float2 a0[2][4], b0[4][2];
            #pragma unroll
            for (int ma = 0; ma < 2; ma++) {
                int r0 = mb + ma * 16 + tq;
                a0[ma][0] = As[r0][kb + tr];
                a0[ma][1] = As[r0 + 8][kb + tr];
                a0[ma][2] = As[r0][kb + tr + 4];
                a0[ma][3] = As[r0 + 8][kb + tr + 4];
            }
            #pragma unroll
            for (int na = 0; na < 4; na++) {
                int n_ = nb + na * 8 + tq;
                b0[na][0] = Bs[n_][kb + tr];
                b0[na][1] = Bs[n_][kb + tr + 4];
            }
            #pragma unroll
            for (int ma = 0; ma < 2; ma++)
                #pragma unroll
                for (int na = 0; na < 4; na++) {
                    uint32_t ah0 = __float_as_uint(a0[ma][0].x), al0 = __float_as_uint(a0[ma][0].y);
                    uint32_t ah1 = __float_as_uint(a0[ma][1].x), al1 = __float_as_uint(a0[ma][1].y);
                    uint32_t ah2 = __float_as_uint(a0[ma][2].x), al2 = __float_as_uint(a0[ma][2].y);
                    uint32_t ah3 = __float_as_uint(a0[ma][3].x), al3 = __float_as_uint(a0[ma][3].y);
                    uint32_t bh0 = __float_as_uint(b0[na][0].x), bl0 = __float_as_uint(b0[na][0].y);
                    uint32_t bh1 = __float_as_uint(b0[na][1].x), bl1 = __float_as_uint(b0[na][1].y);
                    mma_tf32(c[ma][na], ah0, ah1, ah2, ah3, bl0, bl1);
                    mma_tf32(c[ma][na], al0, al1, al2, al3, bh0, bh1);
                    mma_tf32(c[ma][na], ah0, ah1, ah2, ah3, bh0, bh1);
                }
        }
        __syncthreads();
    }
}

// ---------------- fused scores + relations (3xTF32), COMPACT grid ------------
// 832 blocks: b<320 => scores (h, causal tiles); b>=320 => relations.
__global__ void __launch_bounds__(256, 2) scorerel_kernel(
    const float* __restrict__ Q, const float* __restrict__ K,
    const float* __restrict__ QR, const float* __restrict__ KR,
    float* __restrict__ attn, float* __restrict__ relT)
{
    int b = blockIdx.x;
    const float* A;
    const float* B;
    float* C;
    int ldb, m0, n0;
    if (b < 320) {
        int h = b / 20, t = b % 20;
        int my = (t < 2) ? 0 : (t < 6) ? 1 : (t < 12) ? 2 : 3;
        const int basec[4] = {0, 2, 6, 12};
        int nx = t - basec[my];
        m0 = my * 128; n0 = nx * 64;
        A = Q + h * HD; B = K + (h >> 2) * HD; ldb = NKV * HD;
        C = attn + (size_t)h * L * L;
    } else {
        int bb = b - 320;
        int r = bb >> 5, rem = bb & 31;
        m0 = (rem >> 3) * 128; n0 = (rem & 7) * 64;
        A = QR + r * HD; B = KR + r * HD; ldb = NR * HD;
        C = relT + (size_t)r * L * L;
    }

    float c[2][4][4];
    #pragma unroll
    for (int i = 0; i < 2; i++)
        #pragma unroll
        for (int j = 0; j < 4; j++)
            #pragma unroll
            for (int k = 0; k < 4; k++) c[i][j][k] = 0.f;

    mma3x_compute(A, 1024, B, ldb, m0, n0, 64, c);

    int lane = threadIdx.x & 31, warp = threadIdx.x >> 5;
    int tq = lane >> 2, tr = lane & 3;
    int mb = (warp & 3) * 32, nb = (warp >> 2) * 32;
    #pragma unroll
    for (int ma = 0; ma < 2; ma++) {
        int row = m0 + mb + ma * 16 + tq;
        #pragma unroll
        for (int na = 0; na < 4; na++) {
            int col = n0 + nb + na * 8 + 2 * tr;
            *reinterpret_cast<float2*>(&C[(size_t)row * L + col]) =
                make_float2(c[ma][na][0] * 0.125f, c[ma][na][1] * 0.125f);
            *reinterpret_cast<float2*>(&C[(size_t)(row + 8) * L + col]) =
                make_float2(c[ma][na][2] * 0.125f, c[ma][na][3] * 0.125f);
        }
    }
}

// ---------------- causal softmax ---------------------------------------------
__global__ void __launch_bounds__(128) softmax_kernel(float* __restrict__ attn) {
    int row = blockIdx.x;
    int i = row & (L - 1);
    int len = i + 1;
    float4* p4 = reinterpret_cast<float4*>(attn + (size_t)row * L);
    int tid = threadIdx.x;
    int lane = tid & 31, wid = tid >> 5;
    int base = tid * 4;

    float4 v = p4[tid];
    float e0 = (base + 0 < len) ? v.x : -3.0e38f;
    float e1 = (base + 1 < len) ? v.y : -3.0e38f;
    float e2 = (base + 2 < len) ? v.z : -3.0e38f;
    float e3 = (base + 3 < len) ? v.w : -3.0e38f;

    float m = fmaxf(fmaxf(e0, e1), fmaxf(e2, e3));
    #pragma unroll
    for (int off = 16; off > 0; off >>= 1)
        m = fmaxf(m, __shfl_xor_sync(0xFFFFFFFFu, m, off));

    __shared__ float sm[8];
    if (lane == 0) sm[wid] = m;
    __syncthreads();
    m = fmaxf(fmaxf(sm[0], sm[1]), fmaxf(sm[2], sm[3]));

    float x0 = (base + 0 < len) ? __expf(e0 - m) : 0.f;
    float x1 = (base + 1 < len) ? __expf(e1 - m) : 0.f;
    float x2 = (base + 2 < len) ? __expf(e2 - m) : 0.f;
    float x3 = (base + 3 < len) ? __expf(e3 - m) : 0.f;

    float s = x0 + x1 + x2 + x3;
    #pragma unroll
    for (int off = 16; off > 0; off >>= 1)
        s += __shfl_xor_sync(0xFFFFFFFFu, s, off);
    if (lane == 0) sm[4 + wid] = s;
    __syncthreads();
    float inv = 1.f / (sm[4] + sm[5] + sm[6] + sm[7]);

    p4[tid] = make_float4(x0 * inv, x1 * inv, x2 * inv, x3 * inv);
}

// ---- fused: rel transpose-write + partial S, split over j-halves ------------
__global__ void __launch_bounds__(256) s_trans_kernel(
    const float* __restrict__ attn, const float* __restrict__ relT,
    float* __restrict__ rel, float* __restrict__ S, float* __restrict__ S2)
{
    int i = blockIdx.x;
    int jh = blockIdx.y;
    int tid = threadIdx.x;
    int h = tid >> 4, r = tid & 15;
    __shared__ float attnS[16][132];
    __shared__ float relS[16][132];
    float acc = 0.f;
    int jbeg = jh * 256;
    for (int j0 = jbeg; j0 < jbeg + 256; j0 += 128) {
        bool do_acc = (j0 <= i);
        if (do_acc) {
            #pragma unroll
            for (int e = tid; e < 512; e += 256) {
                int hh = e >> 5, q = e & 31;
                *reinterpret_cast<float4*>(&attnS[hh][q * 4]) =
                    *reinterpret_cast<const float4*>(&attn[((size_t)hh * L + i) * L + j0 + q * 4]);
            }
        }
        #pragma unroll
        for (int e = tid; e < 512; e += 256) {
            int rr = e >> 5, q = e & 31;
            *reinterpret_cast<float4*>(&relS[rr][q * 4]) =
                *reinterpret_cast<const float4*>(&relT[((size_t)rr * L + i) * L + j0 + q * 4]);
        }
        __syncthreads();
        #pragma unroll
        for (int e = tid; e < 512; e += 256) {
            int j = e >> 2, rq = e & 3;
            float4 v = make_float4(relS[rq * 4 + 0][j], relS[rq * 4 + 1][j],
                                   relS[rq * 4 + 2][j], relS[rq * 4 + 3][j]);
            *reinterpret_cast<float4*>(&rel[((size_t)i * L + j0 + j) * NR + rq * 4]) = v;
        }
        if (do_acc) {
            #pragma unroll 16
            for (int jj = 0; jj < 128; jj++)
                acc += attnS[h][jj] * relS[r][jj];
        }
        __syncthreads();
    }
    float* So = jh ? S2 : S;
    So[((size_t)i * NH + h) * NR + r] = acc;
}

// ---------------------------------------------------------------------------
extern "C" void kernel_launch(void* const* d_in, const int* in_sizes, int n_in,
                              void* d_out, int out_size) {
    const float* x       = (const float*)d_in[0];
    const float* symbols = (const float*)d_in[1];
    const float* fcos    = (const float*)d_in[2];
    const float* fsin    = (const float*)d_in[3];
    const float* wq_attn = (const float*)d_in[4];
    const float* wk_attn = (const float*)d_in[5];
    const float* wq_rel  = (const float*)d_in[6];
    const float* wk_rel  = (const float*)d_in[7];
    const float* wr      = (const float*)d_in[8];
    const float* wv      = (const float*)d_in[9];
    const float* wo      = (const float*)d_in[10];

    float* out  = (float*)d_out;
    float* attn = out + (size_t)L * NH * HD;
    float* rel  = attn + (size_t)NH * L * L;

    float *Q, *K, *QR, *KR, *SV, *S, *S2, *CTX, *RELT;
    cudaGetSymbolAddress((void**)&Q,  g_Q);
    cudaGetSymbolAddress((void**)&K,  g_K);
    cudaGetSymbolAddress((void**)&QR, g_QR);
    cudaGetSymbolAddress((void**)&KR, g_KR);
    cudaGetSymbolAddress((void**)&SV, g_SV);
    cudaGetSymbolAddress((void**)&S,  g_S);
    cudaGetSymbolAddress((void**)&S2, g_S2);
    cudaGetSymbolAddress((void**)&CTX, g_CTX);
    cudaGetSymbolAddress((void**)&RELT, g_RELT);

    // 1) projections + fused RoPE (double-buffered GEMM)
    proj_mma_kernel<<<dim3(4, 56), 256>>>(x, symbols, wq_attn, wq_rel, wk_rel,
                                          wk_attn, wv, fcos, fsin, Q, K, QR, KR, SV);

    // 2) fused scores + relations (3xTF32, compact 832-block grid)
    scorerel_kernel<<<832, 256>>>(Q, K, QR, KR, attn, RELT);

    // 3) softmax
    softmax_kernel<<<NH * L, 128>>>(attn);

    // 4) fused rel transpose-out + partial S (j-split)
    s_trans_kernel<<<dim3(L, 2), 256>>>(attn, RELT, rel, S, S2);

    // 5) ctx = attn@sv (single-pass tf32) + (S+S2)@wr epilogue
    attended_kernel<<<dim3(4, NH), 256>>>(attn, SV, S, S2, wr, CTX);

    // 6) out = ctx @ wo (double-buffered GEMM)
    out_mma_kernel<<<dim3(4, 16), 256>>>(CTX, wo, out);
}